// round 1
// baseline (speedup 1.0000x reference)
#include <cuda_runtime.h>

// TensorTrain forward, restructured as GEMMs:
//   M1flat[1024,4096] = perm(core1) @ X0      (m = a*32+b, k = d)
//   M2flat[1024,4096] = perm(core2) @ X1
//   V3[32,4096]       = core3[:,:,0] @ X2
//   per-sample: u2 = M2[n]@v3 ; u1 = M1[n]@u2 ; Z[:,n] = C0 @ u1

namespace {
constexpr int NB = 4096;   // batch
constexpr int D  = 512;    // view dim / d_out
constexpr int R  = 32;     // TT rank
constexpr int MF = 1024;   // R*R
}

__device__ float g_M1[MF * NB];   // 16 MB
__device__ float g_M2[MF * NB];   // 16 MB
__device__ float g_V3[R * NB];

// ---------------------------------------------------------------------------
// GEMM: C[m,n] = sum_k core[m>>5, k, m&31] * X[k, n]
// C = g_M1 (which==0) or g_M2 (which==1). 128x128 tile, BK=16, 256 thr, 8x8.
// ---------------------------------------------------------------------------
__global__ __launch_bounds__(256, 2)
void gemm_core_kernel(const float* __restrict__ core,
                      const float* __restrict__ X,
                      int which)
{
    float* __restrict__ C = which ? g_M2 : g_M1;
    constexpr int BK = 16;
    __shared__ float As[BK][128];
    __shared__ float Bs[BK][128];

    const int bn = blockIdx.x * 128;
    const int bm = blockIdx.y * 128;
    const int t  = threadIdx.x;
    const int tx = t & 15;     // 0..15 -> N quads
    const int ty = t >> 4;     // 0..15 -> M quads

    float acc[8][8];
#pragma unroll
    for (int i = 0; i < 8; i++)
#pragma unroll
        for (int j = 0; j < 8; j++) acc[i][j] = 0.f;

    for (int k0 = 0; k0 < D; k0 += BK) {
        // A tile: As[k][m] with permuted global addressing
#pragma unroll
        for (int j = 0; j < 8; j++) {
            int i  = t + j * 256;
            int ml = i & 127, kl = i >> 7;
            int m  = bm + ml;
            As[kl][ml] = core[(m >> 5) * (D * R) + (k0 + kl) * R + (m & 31)];
        }
        // B tile: Bs[k][n]
#pragma unroll
        for (int j = 0; j < 8; j++) {
            int i  = t + j * 256;
            int nl = i & 127, kl = i >> 7;
            Bs[kl][nl] = X[(k0 + kl) * NB + bn + nl];
        }
        __syncthreads();

#pragma unroll
        for (int kk = 0; kk < BK; kk++) {
            const float4* A4 = reinterpret_cast<const float4*>(&As[kk][0]);
            const float4* B4 = reinterpret_cast<const float4*>(&Bs[kk][0]);
            float4 a0 = A4[ty], a1 = A4[ty + 16];
            float4 b0 = B4[tx], b1 = B4[tx + 16];
            float ar[8] = {a0.x, a0.y, a0.z, a0.w, a1.x, a1.y, a1.z, a1.w};
            float br[8] = {b0.x, b0.y, b0.z, b0.w, b1.x, b1.y, b1.z, b1.w};
#pragma unroll
            for (int i = 0; i < 8; i++)
#pragma unroll
                for (int j = 0; j < 8; j++)
                    acc[i][j] += ar[i] * br[j];
        }
        __syncthreads();
    }

    // Write out: rows {ty*4..+3, 64+ty*4..+3}, cols {tx*4..+3, 64+tx*4..+3}
#pragma unroll
    for (int i = 0; i < 8; i++) {
        int rm = bm + ((i < 4) ? (ty * 4 + i) : (64 + ty * 4 + (i - 4)));
        float4 v0 = make_float4(acc[i][0], acc[i][1], acc[i][2], acc[i][3]);
        float4 v1 = make_float4(acc[i][4], acc[i][5], acc[i][6], acc[i][7]);
        *reinterpret_cast<float4*>(&C[rm * NB + bn + tx * 4])      = v0;
        *reinterpret_cast<float4*>(&C[rm * NB + bn + 64 + tx * 4]) = v1;
    }
}

// ---------------------------------------------------------------------------
// V3[a,n] = sum_d core3[a*512+d] * X2[d,n]   (core3 is [32,512,1] => row-major [32,512])
// block: 128 columns, 256 threads; each thread: 16 'a' rows for one column.
// ---------------------------------------------------------------------------
__global__ __launch_bounds__(256)
void v3_kernel(const float* __restrict__ core3, const float* __restrict__ X2)
{
    __shared__ float Xs[32][128];
    const int t  = threadIdx.x;
    const int n0 = blockIdx.x * 128;
    const int nl = t & 127;
    const int ab = (t >> 7) * 16;   // 0 or 16

    float acc[16];
#pragma unroll
    for (int i = 0; i < 16; i++) acc[i] = 0.f;

    for (int d0 = 0; d0 < D; d0 += 32) {
#pragma unroll
        for (int i = 0; i < 16; i++) {
            int idx = t + i * 256;
            Xs[idx >> 7][idx & 127] = X2[(d0 + (idx >> 7)) * NB + n0 + (idx & 127)];
        }
        __syncthreads();
#pragma unroll
        for (int dl = 0; dl < 32; dl++) {
            float x = Xs[dl][nl];
#pragma unroll
            for (int i = 0; i < 16; i++)
                acc[i] += core3[(ab + i) * D + d0 + dl] * x;
        }
        __syncthreads();
    }
#pragma unroll
    for (int i = 0; i < 16; i++)
        g_V3[(ab + i) * NB + n0 + nl] = acc[i];
}

// ---------------------------------------------------------------------------
// Chain + output. Block = 32 samples.
//   u2[a] = sum_b M2flat[a*32+b, n] * v3[b]
//   u1[a] = sum_b M1flat[a*32+b, n] * u2[b]
//   Z[o,n] = sum_a core0[o*32+a] * u1[a]
// ---------------------------------------------------------------------------
__global__ __launch_bounds__(256)
void chain_kernel(const float* __restrict__ core0, float* __restrict__ Z)
{
    __shared__ float tile[256][33];   // 33.8 KB
    __shared__ float v3s[R][33];
    __shared__ float u2s[R][33];
    __shared__ float u1s[R][33];

    const int t  = threadIdx.x;
    const int n0 = blockIdx.x * 32;
    const int s  = t & 31;
    const int al = t >> 5;            // 0..7

    for (int i = t; i < R * 32; i += 256)
        v3s[i >> 5][i & 31] = g_V3[(i >> 5) * NB + n0 + (i & 31)];

    // u2 from M2flat (4 chunks of 256 m-rows)
    for (int c = 0; c < 4; c++) {
#pragma unroll
        for (int i = 0; i < 32; i++) {
            int idx = t + i * 256;
            tile[idx >> 5][idx & 31] = g_M2[(c * 256 + (idx >> 5)) * NB + n0 + (idx & 31)];
        }
        __syncthreads();
        float acc = 0.f;
#pragma unroll
        for (int b = 0; b < 32; b++)
            acc += tile[al * 32 + b][s] * v3s[b][s];
        u2s[c * 8 + al][s] = acc;
        __syncthreads();
    }

    // u1 from M1flat
    for (int c = 0; c < 4; c++) {
#pragma unroll
        for (int i = 0; i < 32; i++) {
            int idx = t + i * 256;
            tile[idx >> 5][idx & 31] = g_M1[(c * 256 + (idx >> 5)) * NB + n0 + (idx & 31)];
        }
        __syncthreads();
        float acc = 0.f;
#pragma unroll
        for (int b = 0; b < 32; b++)
            acc += tile[al * 32 + b][s] * u2s[b][s];
        u1s[c * 8 + al][s] = acc;
        __syncthreads();
    }

    // Z = C0 @ u1 ; each thread covers 64 output rows for its sample s
#pragma unroll 4
    for (int oo = 0; oo < 64; oo++) {
        int o = oo * 8 + al;
        float acc = 0.f;
#pragma unroll
        for (int a = 0; a < R; a++)
            acc += core0[o * R + a] * u1s[a][s];
        Z[o * NB + n0 + s] = acc;
    }
}

// ---------------------------------------------------------------------------
extern "C" void kernel_launch(void* const* d_in, const int* in_sizes, int n_in,
                              void* d_out, int out_size)
{
    const float* X0    = (const float*)d_in[0];
    const float* X1    = (const float*)d_in[1];
    const float* X2    = (const float*)d_in[2];
    const float* core0 = (const float*)d_in[3];
    const float* core1 = (const float*)d_in[4];
    const float* core2 = (const float*)d_in[5];
    const float* core3 = (const float*)d_in[6];
    float* Z = (float*)d_out;

    dim3 g(NB / 128, MF / 128);                 // (32, 8)
    gemm_core_kernel<<<g, 256>>>(core1, X0, 0); // -> g_M1
    gemm_core_kernel<<<g, 256>>>(core2, X1, 1); // -> g_M2
    v3_kernel<<<NB / 128, 256>>>(core3, X2);    // -> g_V3
    chain_kernel<<<NB / 32, 256>>>(core0, Z);   // -> Z
}

// round 2
// speedup vs baseline: 1.0044x; 1.0044x over previous
#include <cuda_runtime.h>

// TensorTrain forward, restructured as GEMMs:
//   M1flat[1024,4096] = perm(core1) @ X0      (m = a*32+b, k = d)
//   M2flat[1024,4096] = perm(core2) @ X1
//   V3[32,4096]       = core3[:,:,0] @ X2
//   per-sample: u2 = M2[n]@v3 ; u1 = M1[n]@u2 ; Z[:,n] = C0 @ u1

namespace {
constexpr int NB = 4096;   // batch
constexpr int D  = 512;    // view dim / d_out
constexpr int R  = 32;     // TT rank
constexpr int MF = 1024;   // R*R
}

__device__ float g_M1[MF * NB];   // 16 MB
__device__ float g_M2[MF * NB];   // 16 MB
__device__ float g_V3[R * NB];

// ---------------------------------------------------------------------------
// GEMM: C[m,n] = sum_k core[m>>5, k, m&31] * X[k, n]
// C = g_M1 (which==0) or g_M2 (which==1). 128x128 tile, BK=16, 256 thr, 8x8.
// ---------------------------------------------------------------------------
__global__ __launch_bounds__(256, 2)
void gemm_core_kernel(const float* __restrict__ core,
                      const float* __restrict__ X,
                      int which)
{
    float* __restrict__ C = which ? g_M2 : g_M1;
    constexpr int BK = 16;
    __shared__ float As[BK][128];
    __shared__ float Bs[BK][128];

    const int bn = blockIdx.x * 128;
    const int bm = blockIdx.y * 128;
    const int t  = threadIdx.x;
    const int tx = t & 15;     // 0..15 -> N quads
    const int ty = t >> 4;     // 0..15 -> M quads

    float acc[8][8];
#pragma unroll
    for (int i = 0; i < 8; i++)
#pragma unroll
        for (int j = 0; j < 8; j++) acc[i][j] = 0.f;

    for (int k0 = 0; k0 < D; k0 += BK) {
        // A tile: As[k][m] with permuted global addressing
#pragma unroll
        for (int j = 0; j < 8; j++) {
            int i  = t + j * 256;
            int ml = i & 127, kl = i >> 7;
            int m  = bm + ml;
            As[kl][ml] = core[(m >> 5) * (D * R) + (k0 + kl) * R + (m & 31)];
        }
        // B tile: Bs[k][n]
#pragma unroll
        for (int j = 0; j < 8; j++) {
            int i  = t + j * 256;
            int nl = i & 127, kl = i >> 7;
            Bs[kl][nl] = X[(k0 + kl) * NB + bn + nl];
        }
        __syncthreads();

#pragma unroll
        for (int kk = 0; kk < BK; kk++) {
            const float4* A4 = reinterpret_cast<const float4*>(&As[kk][0]);
            const float4* B4 = reinterpret_cast<const float4*>(&Bs[kk][0]);
            float4 a0 = A4[ty], a1 = A4[ty + 16];
            float4 b0 = B4[tx], b1 = B4[tx + 16];
            float ar[8] = {a0.x, a0.y, a0.z, a0.w, a1.x, a1.y, a1.z, a1.w};
            float br[8] = {b0.x, b0.y, b0.z, b0.w, b1.x, b1.y, b1.z, b1.w};
#pragma unroll
            for (int i = 0; i < 8; i++)
#pragma unroll
                for (int j = 0; j < 8; j++)
                    acc[i][j] += ar[i] * br[j];
        }
        __syncthreads();
    }

    // Write out: rows {ty*4..+3, 64+ty*4..+3}, cols {tx*4..+3, 64+tx*4..+3}
#pragma unroll
    for (int i = 0; i < 8; i++) {
        int rm = bm + ((i < 4) ? (ty * 4 + i) : (64 + ty * 4 + (i - 4)));
        float4 v0 = make_float4(acc[i][0], acc[i][1], acc[i][2], acc[i][3]);
        float4 v1 = make_float4(acc[i][4], acc[i][5], acc[i][6], acc[i][7]);
        *reinterpret_cast<float4*>(&C[rm * NB + bn + tx * 4])      = v0;
        *reinterpret_cast<float4*>(&C[rm * NB + bn + 64 + tx * 4]) = v1;
    }
}

// ---------------------------------------------------------------------------
// V3[a,n] = sum_d core3[a*512+d] * X2[d,n]   (core3 is [32,512,1] => row-major [32,512])
// block: 128 columns, 256 threads; each thread: 16 'a' rows for one column.
// ---------------------------------------------------------------------------
__global__ __launch_bounds__(256)
void v3_kernel(const float* __restrict__ core3, const float* __restrict__ X2)
{
    __shared__ float Xs[32][128];
    const int t  = threadIdx.x;
    const int n0 = blockIdx.x * 128;
    const int nl = t & 127;
    const int ab = (t >> 7) * 16;   // 0 or 16

    float acc[16];
#pragma unroll
    for (int i = 0; i < 16; i++) acc[i] = 0.f;

    for (int d0 = 0; d0 < D; d0 += 32) {
#pragma unroll
        for (int i = 0; i < 16; i++) {
            int idx = t + i * 256;
            Xs[idx >> 7][idx & 127] = X2[(d0 + (idx >> 7)) * NB + n0 + (idx & 127)];
        }
        __syncthreads();
#pragma unroll
        for (int dl = 0; dl < 32; dl++) {
            float x = Xs[dl][nl];
#pragma unroll
            for (int i = 0; i < 16; i++)
                acc[i] += core3[(ab + i) * D + d0 + dl] * x;
        }
        __syncthreads();
    }
#pragma unroll
    for (int i = 0; i < 16; i++)
        g_V3[(ab + i) * NB + n0 + nl] = acc[i];
}

// ---------------------------------------------------------------------------
// Chain + output. Block = 32 samples.
//   u2[a] = sum_b M2flat[a*32+b, n] * v3[b]
//   u1[a] = sum_b M1flat[a*32+b, n] * u2[b]
//   Z[o,n] = sum_a core0[o*32+a] * u1[a]
// ---------------------------------------------------------------------------
__global__ __launch_bounds__(256)
void chain_kernel(const float* __restrict__ core0, float* __restrict__ Z)
{
    __shared__ float tile[256][33];   // 33.8 KB
    __shared__ float v3s[R][33];
    __shared__ float u2s[R][33];
    __shared__ float u1s[R][33];

    const int t  = threadIdx.x;
    const int n0 = blockIdx.x * 32;
    const int s  = t & 31;
    const int al = t >> 5;            // 0..7

    for (int i = t; i < R * 32; i += 256)
        v3s[i >> 5][i & 31] = g_V3[(i >> 5) * NB + n0 + (i & 31)];

    // u2 from M2flat (4 chunks of 256 m-rows)
    for (int c = 0; c < 4; c++) {
#pragma unroll
        for (int i = 0; i < 32; i++) {
            int idx = t + i * 256;
            tile[idx >> 5][idx & 31] = g_M2[(c * 256 + (idx >> 5)) * NB + n0 + (idx & 31)];
        }
        __syncthreads();
        float acc = 0.f;
#pragma unroll
        for (int b = 0; b < 32; b++)
            acc += tile[al * 32 + b][s] * v3s[b][s];
        u2s[c * 8 + al][s] = acc;
        __syncthreads();
    }

    // u1 from M1flat
    for (int c = 0; c < 4; c++) {
#pragma unroll
        for (int i = 0; i < 32; i++) {
            int idx = t + i * 256;
            tile[idx >> 5][idx & 31] = g_M1[(c * 256 + (idx >> 5)) * NB + n0 + (idx & 31)];
        }
        __syncthreads();
        float acc = 0.f;
#pragma unroll
        for (int b = 0; b < 32; b++)
            acc += tile[al * 32 + b][s] * u2s[b][s];
        u1s[c * 8 + al][s] = acc;
        __syncthreads();
    }

    // Z = C0 @ u1 ; each thread covers 64 output rows for its sample s
#pragma unroll 4
    for (int oo = 0; oo < 64; oo++) {
        int o = oo * 8 + al;
        float acc = 0.f;
#pragma unroll
        for (int a = 0; a < R; a++)
            acc += core0[o * R + a] * u1s[a][s];
        Z[o * NB + n0 + s] = acc;
    }
}

// ---------------------------------------------------------------------------
extern "C" void kernel_launch(void* const* d_in, const int* in_sizes, int n_in,
                              void* d_out, int out_size)
{
    const float* X0    = (const float*)d_in[0];
    const float* X1    = (const float*)d_in[1];
    const float* X2    = (const float*)d_in[2];
    const float* core0 = (const float*)d_in[3];
    const float* core1 = (const float*)d_in[4];
    const float* core2 = (const float*)d_in[5];
    const float* core3 = (const float*)d_in[6];
    float* Z = (float*)d_out;

    dim3 g(NB / 128, MF / 128);                 // (32, 8)
    gemm_core_kernel<<<g, 256>>>(core1, X0, 0); // -> g_M1
    gemm_core_kernel<<<g, 256>>>(core2, X1, 1); // -> g_M2
    v3_kernel<<<NB / 128, 256>>>(core3, X2);    // -> g_V3
    chain_kernel<<<NB / 32, 256>>>(core0, Z);   // -> Z
}

// round 6
// speedup vs baseline: 2.0365x; 2.0276x over previous
#include <cuda_runtime.h>
#include <cuda_bf16.h>
#include <cstdint>

// ============================================================================
// TensorTrain forward via mma.sync (bf16 3-split) with fused rank contraction.
//   v3 = core3 @ X2                              [32,4096]
//   GEMM pass0: perm(core2)@X1 tiles, epi * v3 -> u2  [32,4096]
//   GEMM pass1: perm(core1)@X0 tiles, epi * u2 -> u1  [32,4096]
//   Z = core0 @ u1                               [512,4096]
//
// Packed operand layout (per (tile, kc) block of 8192 u32 words):
//   word[split*4096 + row*32 + (kp ^ ((row&7)<<2))] = bf16pair(M[row][2kp], M[row][2kp+1])
//   split 0 = bf16(x) ("hi"), split 1 = bf16(x - hi) ("lo").
// NOTE: __device__ globals are ONLY referenced from device code (selected by
// an integer flag) — host code never takes their address.
// ============================================================================

namespace {
constexpr int NB = 4096;
constexpr int D  = 512;
constexpr int R  = 32;
constexpr int SM_SCALE = 0;       // sS: 32 x 132 f32 = 16896 B
constexpr int SM_ST    = 17408;   // two 64 KB stages (A 32K | B 32K each)
constexpr int SM_TOTAL = SM_ST + 2 * 65536;   // 148480
}

__device__ float g_V3[R * NB];
__device__ float g_u2[R * NB];
__device__ float g_u1[R * NB];
// A blocks: [mt(8)][kc(8)] x 8192 words ; B blocks: [nt(32)][kc(8)] x 8192 words
__device__ uint32_t g_A1[8 * 8 * 8192];
__device__ uint32_t g_A2[8 * 8 * 8192];
__device__ uint32_t g_B0[32 * 8 * 8192];
__device__ uint32_t g_B1[32 * 8 * 8192];

// ---------------------------------------------------------------------------
__device__ __forceinline__ uint32_t smem_u32(const void* p) {
    uint32_t a;
    asm("{ .reg .u64 t; cvta.to.shared.u64 t, %1; cvt.u32.u64 %0, t; }" : "=r"(a) : "l"(p));
    return a;
}
__device__ __forceinline__ void cp16(uint32_t saddr, const void* g) {
    asm volatile("cp.async.cg.shared.global [%0], [%1], 16;" :: "r"(saddr), "l"(g) : "memory");
}
#define CP_COMMIT() asm volatile("cp.async.commit_group;" ::: "memory")

__device__ __forceinline__ void mma16816(float* d, const uint32_t* a, const uint32_t* b) {
    asm volatile(
        "mma.sync.aligned.m16n8k16.row.col.f32.bf16.bf16.f32 "
        "{%0,%1,%2,%3}, {%4,%5,%6,%7}, {%8,%9}, {%0,%1,%2,%3};"
        : "+f"(d[0]), "+f"(d[1]), "+f"(d[2]), "+f"(d[3])
        : "r"(a[0]), "r"(a[1]), "r"(a[2]), "r"(a[3]), "r"(b[0]), "r"(b[1]));
}
__device__ __forceinline__ uint32_t pack_bf16x2(float x0, float x1, int split) {
    __nv_bfloat16 h0 = __float2bfloat16(x0), h1 = __float2bfloat16(x1);
    if (split == 0)
        return ((uint32_t)__bfloat16_as_ushort(h1) << 16) | __bfloat16_as_ushort(h0);
    __nv_bfloat16 l0 = __float2bfloat16(x0 - __bfloat162float(h0));
    __nv_bfloat16 l1 = __float2bfloat16(x1 - __bfloat162float(h1));
    return ((uint32_t)__bfloat16_as_ushort(l1) << 16) | __bfloat16_as_ushort(l0);
}

// ---------------------------------------------------------------------------
// Pack core[a,k,b] (32x512x32 f32) -> A blocks. grid (mt=8, kc=8), 256 thr.
// which: 1 -> g_A1, 2 -> g_A2.
// ---------------------------------------------------------------------------
__global__ __launch_bounds__(256)
void pack_core_kernel(const float* __restrict__ core, int which)
{
    uint32_t* __restrict__ out = (which == 1) ? g_A1 : g_A2;
    __shared__ float sC[4 * 2112];    // [a_loc][kloc(64) stride 33][b(32)]
    const int t = threadIdx.x, mt = blockIdx.x, kc = blockIdx.y;
#pragma unroll
    for (int i = 0; i < 32; i++) {
        int idx = t + i * 256;                 // 0..8191
        int a_loc = idx >> 11, rem = idx & 2047;
        int kloc = rem >> 5, b = rem & 31;
        sC[a_loc * 2112 + kloc * 33 + b] =
            core[(mt * 4 + a_loc) * (D * R) + kc * 2048 + rem];
    }
    __syncthreads();
    uint32_t* dst = out + (mt * 8 + kc) * 8192;
#pragma unroll
    for (int i = 0; i < 32; i++) {
        int w = t + i * 256;
        int split = w >> 12, m_loc = (w >> 5) & 127, kp = w & 31;
        int a_loc = m_loc >> 5, b = m_loc & 31, k0 = kp * 2;
        float x0 = sC[a_loc * 2112 + k0 * 33 + b];
        float x1 = sC[a_loc * 2112 + (k0 + 1) * 33 + b];
        dst[split * 4096 + m_loc * 32 + (kp ^ ((m_loc & 7) << 2))] =
            pack_bf16x2(x0, x1, split);
    }
}

// ---------------------------------------------------------------------------
// Pack X[k,n] (512x4096 f32) -> B blocks. grid (nt=32, kc=8), 256 thr.
// which: 0 -> g_B0, 1 -> g_B1.
// ---------------------------------------------------------------------------
__global__ __launch_bounds__(256)
void pack_x_kernel(const float* __restrict__ X, int which)
{
    uint32_t* __restrict__ out = (which == 0) ? g_B0 : g_B1;
    __shared__ float sX[64 * 129];
    const int t = threadIdx.x, nt = blockIdx.x, kc = blockIdx.y;
#pragma unroll
    for (int i = 0; i < 32; i++) {
        int idx = t + i * 256;
        int k = idx >> 7, nl = idx & 127;
        sX[k * 129 + nl] = X[(kc * 64 + k) * NB + nt * 128 + nl];
    }
    __syncthreads();
    uint32_t* dst = out + (nt * 8 + kc) * 8192;
#pragma unroll
    for (int i = 0; i < 32; i++) {
        int w = t + i * 256;
        int split = w >> 12, n_loc = (w >> 5) & 127, kp = w & 31, k0 = kp * 2;
        float x0 = sX[k0 * 129 + n_loc];
        float x1 = sX[(k0 + 1) * 129 + n_loc];
        dst[split * 4096 + n_loc * 32 + (kp ^ ((n_loc & 7) << 2))] =
            pack_bf16x2(x0, x1, split);
    }
}

// ---------------------------------------------------------------------------
// v3[a,n] = sum_d core3[a,d] * X2[d,n]   (writes g_V3 directly)
// ---------------------------------------------------------------------------
__global__ __launch_bounds__(256)
void v3_kernel(const float* __restrict__ core3, const float* __restrict__ X2)
{
    __shared__ float Xs[32][128];
    const int t = threadIdx.x, n0 = blockIdx.x * 128;
    const int nl = t & 127, ab = (t >> 7) * 16;
    float acc[16];
#pragma unroll
    for (int i = 0; i < 16; i++) acc[i] = 0.f;
    for (int d0 = 0; d0 < D; d0 += 32) {
#pragma unroll
        for (int i = 0; i < 16; i++) {
            int idx = t + i * 256;
            Xs[idx >> 7][idx & 127] = X2[(d0 + (idx >> 7)) * NB + n0 + (idx & 127)];
        }
        __syncthreads();
#pragma unroll
        for (int dl = 0; dl < 32; dl++) {
            float x = Xs[dl][nl];
#pragma unroll
            for (int i = 0; i < 16; i++)
                acc[i] += core3[(ab + i) * D + d0 + dl] * x;
        }
        __syncthreads();
    }
#pragma unroll
    for (int i = 0; i < 16; i++)
        g_V3[(ab + i) * NB + n0 + nl] = acc[i];
}

// ---------------------------------------------------------------------------
// Tensor GEMM (bf16 3-split) + fused contraction epilogue.
// grid (nt=32, mt=8), 256 thr: warp wm=warp&3 (M32 strip), wn=warp>>2 (N64).
// pass 0: A=g_A2, B=g_B1, scale=g_V3, out=g_u2
// pass 1: A=g_A1, B=g_B0, scale=g_u2, out=g_u1
// out[a, n] = sum_b C[a*32+b, n] * scale[b, n],  a = mt*4 + wm.
// ---------------------------------------------------------------------------
__global__ __launch_bounds__(256)
void tt_gemm_kernel(int pass)
{
    const uint32_t* __restrict__ Apk   = (pass == 0) ? g_A2 : g_A1;
    const uint32_t* __restrict__ Bpk   = (pass == 0) ? g_B1 : g_B0;
    const float*    __restrict__ scale = (pass == 0) ? g_V3 : g_u2;
    float*          __restrict__ out   = (pass == 0) ? g_u2 : g_u1;

    extern __shared__ char smem[];
    const int t = threadIdx.x, warp = t >> 5, lane = t & 31;
    const int wm = warp & 3, wn = warp >> 2;
    const int g = lane >> 2, c = lane & 3;
    const int nt = blockIdx.x, mt = blockIdx.y;
    const uint32_t sbase = smem_u32(smem);
    const uint32_t xg = (uint32_t)(g << 2);

    float* sS = (float*)(smem + SM_SCALE);
#pragma unroll
    for (int i = 0; i < 16; i++) {
        int idx = t + i * 256;
        sS[(idx >> 7) * 132 + (idx & 127)] = scale[(idx >> 7) * NB + nt * 128 + (idx & 127)];
    }

    const uint32_t* Asrc = Apk + mt * 65536;
    const uint32_t* Bsrc = Bpk + nt * 65536;

    float acc[2][8][4];
#pragma unroll
    for (int i = 0; i < 2; i++)
#pragma unroll
        for (int j = 0; j < 8; j++)
#pragma unroll
            for (int q = 0; q < 4; q++) acc[i][j][q] = 0.f;

    // prologue: stage 0 <- kc 0
    {
        uint32_t sd = sbase + SM_ST;
        const uint4* a4 = (const uint4*)(Asrc);
        const uint4* b4 = (const uint4*)(Bsrc);
#pragma unroll
        for (int j = 0; j < 8; j++) cp16(sd + (t + j * 256) * 16, a4 + t + j * 256);
#pragma unroll
        for (int j = 0; j < 8; j++) cp16(sd + 32768 + (t + j * 256) * 16, b4 + t + j * 256);
        CP_COMMIT();
    }

    for (int kc = 0; kc < 8; kc++) {
        if (kc > 0) __syncthreads();         // prior compute done before refill
        if (kc < 7) {
            uint32_t sd = sbase + SM_ST + ((kc + 1) & 1) * 65536;
            const uint4* a4 = (const uint4*)(Asrc + (kc + 1) * 8192);
            const uint4* b4 = (const uint4*)(Bsrc + (kc + 1) * 8192);
#pragma unroll
            for (int j = 0; j < 8; j++) cp16(sd + (t + j * 256) * 16, a4 + t + j * 256);
#pragma unroll
            for (int j = 0; j < 8; j++) cp16(sd + 32768 + (t + j * 256) * 16, b4 + t + j * 256);
            CP_COMMIT();
            asm volatile("cp.async.wait_group 1;" ::: "memory");
        } else {
            asm volatile("cp.async.wait_group 0;" ::: "memory");
        }
        __syncthreads();

        const uint32_t* sA = (const uint32_t*)(smem + SM_ST + (kc & 1) * 65536);
        const uint32_t* sB = sA + 8192;

#pragma unroll
        for (int ks = 0; ks < 4; ks++) {
            const int kp0 = ks * 8 + c;          // k = 2*kp0, 2*kp0+1
            const int kp1 = kp0 + 4;             // k = 2*kp0+8, +9
            const int o0 = kp0 ^ xg, o1 = kp1 ^ xg;

            uint32_t bh[8][2], bl[8][2];
#pragma unroll
            for (int j = 0; j < 8; j++) {
                int nb = (wn * 64 + j * 8 + g) * 32;
                bh[j][0] = sB[nb + o0];
                bh[j][1] = sB[nb + o1];
                bl[j][0] = sB[4096 + nb + o0];
                bl[j][1] = sB[4096 + nb + o1];
            }
            uint32_t ah[2][4], al[2][4];
#pragma unroll
            for (int i = 0; i < 2; i++) {
                int r0 = ((wm * 2 + i) * 16 + g) * 32;
                int r1 = r0 + 8 * 32;
                ah[i][0] = sA[r0 + o0];
                ah[i][1] = sA[r1 + o0];
                ah[i][2] = sA[r0 + o1];
                ah[i][3] = sA[r1 + o1];
                al[i][0] = sA[4096 + r0 + o0];
                al[i][1] = sA[4096 + r1 + o0];
                al[i][2] = sA[4096 + r0 + o1];
                al[i][3] = sA[4096 + r1 + o1];
            }
#pragma unroll
            for (int i = 0; i < 2; i++)
#pragma unroll
                for (int j = 0; j < 8; j++) mma16816(acc[i][j], ah[i], bh[j]);
#pragma unroll
            for (int i = 0; i < 2; i++)
#pragma unroll
                for (int j = 0; j < 8; j++) mma16816(acc[i][j], ah[i], bl[j]);
#pragma unroll
            for (int i = 0; i < 2; i++)
#pragma unroll
                for (int j = 0; j < 8; j++) mma16816(acc[i][j], al[i], bh[j]);
        }
    }

    // epilogue: contract over b = rows of the warp's 32-row strip
    const int a = mt * 4 + wm;
    float* dst = out + a * NB + nt * 128 + wn * 64;
#pragma unroll
    for (int j = 0; j < 8; j++) {
        int col0 = wn * 64 + j * 8 + c * 2;
        float p0 = 0.f, p1 = 0.f;
#pragma unroll
        for (int i = 0; i < 2; i++) {
            int b0 = i * 16 + g, b1 = b0 + 8;
            p0 += acc[i][j][0] * sS[b0 * 132 + col0] + acc[i][j][2] * sS[b1 * 132 + col0];
            p1 += acc[i][j][1] * sS[b0 * 132 + col0 + 1] + acc[i][j][3] * sS[b1 * 132 + col0 + 1];
        }
#pragma unroll
        for (int off = 4; off <= 16; off <<= 1) {
            p0 += __shfl_xor_sync(0xffffffffu, p0, off);
            p1 += __shfl_xor_sync(0xffffffffu, p1, off);
        }
        if (g == 0)
            *(float2*)&dst[j * 8 + c * 2] = make_float2(p0, p1);
    }
}

// ---------------------------------------------------------------------------
// Z[o,n] = sum_a core0[o*32+a] * u1[a,n]   (reads g_u1 directly)
// ---------------------------------------------------------------------------
__global__ __launch_bounds__(256)
void z_kernel(const float* __restrict__ core0, float* __restrict__ Z)
{
    __shared__ float cs[64 * 32];
    __shared__ float u1s[32][133];
    const int t = threadIdx.x, nt = blockIdx.x, og = blockIdx.y;
    const int n0 = nt * 128;
#pragma unroll
    for (int i = 0; i < 8; i++)
        cs[i * 256 + t] = core0[og * 64 * 32 + i * 256 + t];
#pragma unroll
    for (int i = 0; i < 16; i++) {
        int idx = t + i * 256;
        u1s[idx >> 7][idx & 127] = g_u1[(idx >> 7) * NB + n0 + (idx & 127)];
    }
    __syncthreads();
    const int j = t & 127, to = t >> 7;
    float u1r[32];
#pragma unroll
    for (int a = 0; a < 32; a++) u1r[a] = u1s[a][j];
#pragma unroll 4
    for (int oo = 0; oo < 32; oo++) {
        int ol = to * 32 + oo;
        float acc = 0.f;
#pragma unroll
        for (int a = 0; a < 32; a++)
            acc += cs[ol * 32 + a] * u1r[a];
        Z[(og * 64 + ol) * NB + n0 + j] = acc;
    }
}

// ---------------------------------------------------------------------------
extern "C" void kernel_launch(void* const* d_in, const int* in_sizes, int n_in,
                              void* d_out, int out_size)
{
    const float* X0    = (const float*)d_in[0];
    const float* X1    = (const float*)d_in[1];
    const float* X2    = (const float*)d_in[2];
    const float* core0 = (const float*)d_in[3];
    const float* core1 = (const float*)d_in[4];
    const float* core2 = (const float*)d_in[5];
    const float* core3 = (const float*)d_in[6];
    float* Z = (float*)d_out;

    static bool attr_done = false;
    if (!attr_done) {
        cudaFuncSetAttribute(tt_gemm_kernel,
                             cudaFuncAttributeMaxDynamicSharedMemorySize, SM_TOTAL);
        attr_done = true;
    }

    pack_core_kernel<<<dim3(8, 8), 256>>>(core1, 1);
    pack_core_kernel<<<dim3(8, 8), 256>>>(core2, 2);
    pack_x_kernel<<<dim3(32, 8), 256>>>(X0, 0);
    pack_x_kernel<<<dim3(32, 8), 256>>>(X1, 1);
    v3_kernel<<<32, 256>>>(core3, X2);
    tt_gemm_kernel<<<dim3(32, 8), 256, SM_TOTAL>>>(0);  // core2 x X1, scale v3 -> u2
    tt_gemm_kernel<<<dim3(32, 8), 256, SM_TOTAL>>>(1);  // core1 x X0, scale u2 -> u1
    z_kernel<<<dim3(32, 8), 256>>>(core0, Z);
}

// round 7
// speedup vs baseline: 2.0491x; 1.0062x over previous
#include <cuda_runtime.h>
#include <cuda_bf16.h>
#include <cstdint>

// ============================================================================
// TensorTrain forward via mma.sync (bf16 3-split) with fused rank contraction.
//   v3 = core3 @ X2                                   [32,4096]
//   GEMM pass0: perm(core2)@X1 tiles, epi * v3 -> u2  [32,4096]
//   GEMM pass1: perm(core1)@X0 tiles, epi * u2 -> u1  [32,4096]
//   Z = core0 @ u1                                    [512,4096]
//
// Packed operand layout, per (tile, kc) block of 4096 u32 words (kc = 32 k):
//   word[split*2048 + row*16 + (kp ^ ((row&3)<<2))] = bf16pair(M[row][2kp], M[row][2kp+1])
//   kp in 0..15, row in 0..127. split0 = bf16(x), split1 = bf16(x - hi).
//   16B groups stay contiguous (XOR touches bits >=2 only) -> ldmatrix-able,
//   and the 8 rows of each 8x8 matrix land on distinct bank groups.
// __device__ globals are ONLY referenced from device code (selected by flag).
// ============================================================================

namespace {
constexpr int NB = 4096;
constexpr int D  = 512;
constexpr int R  = 32;
constexpr int SM_SCALE = 0;       // sS: 32 x 132 f32 = 16896 B
constexpr int SM_ST    = 17408;   // two 32 KB stages (A 16K | B 16K each)
constexpr int SM_TOTAL = SM_ST + 2 * 32768;   // 82944 -> 2 CTAs/SM
}

__device__ float g_V3[R * NB];
__device__ float g_u2[R * NB];
__device__ float g_u1[R * NB];
// A blocks: [mt(8)][kc(16)] x 4096 words ; B blocks: [nt(32)][kc(16)] x 4096 words
__device__ uint32_t g_A1[8 * 16 * 4096];
__device__ uint32_t g_A2[8 * 16 * 4096];
__device__ uint32_t g_B0[32 * 16 * 4096];
__device__ uint32_t g_B1[32 * 16 * 4096];

// ---------------------------------------------------------------------------
__device__ __forceinline__ uint32_t smem_u32(const void* p) {
    uint32_t a;
    asm("{ .reg .u64 t; cvta.to.shared.u64 t, %1; cvt.u32.u64 %0, t; }" : "=r"(a) : "l"(p));
    return a;
}
__device__ __forceinline__ void cp16(uint32_t saddr, const void* g) {
    asm volatile("cp.async.cg.shared.global [%0], [%1], 16;" :: "r"(saddr), "l"(g) : "memory");
}
#define CP_COMMIT() asm volatile("cp.async.commit_group;" ::: "memory")

__device__ __forceinline__ void mma16816(float* d, const uint32_t* a, const uint32_t* b) {
    asm volatile(
        "mma.sync.aligned.m16n8k16.row.col.f32.bf16.bf16.f32 "
        "{%0,%1,%2,%3}, {%4,%5,%6,%7}, {%8,%9}, {%0,%1,%2,%3};"
        : "+f"(d[0]), "+f"(d[1]), "+f"(d[2]), "+f"(d[3])
        : "r"(a[0]), "r"(a[1]), "r"(a[2]), "r"(a[3]), "r"(b[0]), "r"(b[1]));
}
__device__ __forceinline__ void ldsm4(uint32_t* r, uint32_t saddr) {
    asm volatile("ldmatrix.sync.aligned.m8n8.x4.shared.b16 {%0,%1,%2,%3}, [%4];"
                 : "=r"(r[0]), "=r"(r[1]), "=r"(r[2]), "=r"(r[3]) : "r"(saddr));
}
__device__ __forceinline__ uint32_t pack_bf16x2(float x0, float x1, int split) {
    __nv_bfloat16 h0 = __float2bfloat16(x0), h1 = __float2bfloat16(x1);
    if (split == 0)
        return ((uint32_t)__bfloat16_as_ushort(h1) << 16) | __bfloat16_as_ushort(h0);
    __nv_bfloat16 l0 = __float2bfloat16(x0 - __bfloat162float(h0));
    __nv_bfloat16 l1 = __float2bfloat16(x1 - __bfloat162float(h1));
    return ((uint32_t)__bfloat16_as_ushort(l1) << 16) | __bfloat16_as_ushort(l0);
}

// ---------------------------------------------------------------------------
// Pack core[a,k,b] (32x512x32 f32) -> A blocks. grid (mt=8, kc=16), 256 thr.
// which: 1 -> g_A1, 2 -> g_A2.  Block covers rows m=mt*128..+127, k=kc*32..+31.
// ---------------------------------------------------------------------------
__global__ __launch_bounds__(256)
void pack_core_kernel(const float* __restrict__ core, int which)
{
    uint32_t* __restrict__ out = (which == 1) ? g_A1 : g_A2;
    __shared__ float sC[4 * 1056];    // [a_loc][kloc(32) stride 33][b(32)]
    const int t = threadIdx.x, mt = blockIdx.x, kc = blockIdx.y;
#pragma unroll
    for (int i = 0; i < 16; i++) {
        int idx = t + i * 256;                 // 0..4095
        int a_loc = idx >> 10, rem = idx & 1023;
        int kloc = rem >> 5, b = rem & 31;
        sC[a_loc * 1056 + kloc * 33 + b] =
            core[(mt * 4 + a_loc) * (D * R) + kc * 1024 + rem];
    }
    __syncthreads();
    uint32_t* dst = out + (mt * 16 + kc) * 4096;
#pragma unroll
    for (int i = 0; i < 16; i++) {
        int w = t + i * 256;
        int split = w >> 11, rem = w & 2047;
        int m_loc = rem >> 4, wsw = rem & 15;
        int kp = wsw ^ ((m_loc & 3) << 2);
        int a_loc = m_loc >> 5, b = m_loc & 31, k0 = kp * 2;
        float x0 = sC[a_loc * 1056 + k0 * 33 + b];
        float x1 = sC[a_loc * 1056 + (k0 + 1) * 33 + b];
        dst[w] = pack_bf16x2(x0, x1, split);
    }
}

// ---------------------------------------------------------------------------
// Pack X[k,n] (512x4096 f32) -> B blocks. grid (nt=32, kc=16), 256 thr.
// which: 0 -> g_B0, 1 -> g_B1.
// ---------------------------------------------------------------------------
__global__ __launch_bounds__(256)
void pack_x_kernel(const float* __restrict__ X, int which)
{
    uint32_t* __restrict__ out = (which == 0) ? g_B0 : g_B1;
    __shared__ float sX[32 * 129];
    const int t = threadIdx.x, nt = blockIdx.x, kc = blockIdx.y;
#pragma unroll
    for (int i = 0; i < 16; i++) {
        int idx = t + i * 256;
        int k = idx >> 7, nl = idx & 127;
        sX[k * 129 + nl] = X[(kc * 32 + k) * NB + nt * 128 + nl];
    }
    __syncthreads();
    uint32_t* dst = out + (nt * 16 + kc) * 4096;
#pragma unroll
    for (int i = 0; i < 16; i++) {
        int w = t + i * 256;
        int split = w >> 11, rem = w & 2047;
        int n_loc = rem >> 4, wsw = rem & 15;
        int kp = wsw ^ ((n_loc & 3) << 2);
        int k0 = kp * 2;
        float x0 = sX[k0 * 129 + n_loc];
        float x1 = sX[(k0 + 1) * 129 + n_loc];
        dst[w] = pack_bf16x2(x0, x1, split);
    }
}

// ---------------------------------------------------------------------------
// v3[a,n] = sum_d core3[a,d] * X2[d,n]   (writes g_V3 directly)
// ---------------------------------------------------------------------------
__global__ __launch_bounds__(256)
void v3_kernel(const float* __restrict__ core3, const float* __restrict__ X2)
{
    __shared__ float Xs[32][128];
    const int t = threadIdx.x, n0 = blockIdx.x * 128;
    const int nl = t & 127, ab = (t >> 7) * 16;
    float acc[16];
#pragma unroll
    for (int i = 0; i < 16; i++) acc[i] = 0.f;
    for (int d0 = 0; d0 < D; d0 += 32) {
#pragma unroll
        for (int i = 0; i < 16; i++) {
            int idx = t + i * 256;
            Xs[idx >> 7][idx & 127] = X2[(d0 + (idx >> 7)) * NB + n0 + (idx & 127)];
        }
        __syncthreads();
#pragma unroll
        for (int dl = 0; dl < 32; dl++) {
            float x = Xs[dl][nl];
#pragma unroll
            for (int i = 0; i < 16; i++)
                acc[i] += core3[(ab + i) * D + d0 + dl] * x;
        }
        __syncthreads();
    }
#pragma unroll
    for (int i = 0; i < 16; i++)
        g_V3[(ab + i) * NB + n0 + nl] = acc[i];
}

// ---------------------------------------------------------------------------
// Tensor GEMM (bf16 3-split, ldmatrix) + fused contraction epilogue.
// grid (nt=32, mt=8), 256 thr, 2 CTAs/SM. warp wm=warp&3 (M32), wn=warp>>2 (N64).
// pass 0: A=g_A2, B=g_B1, scale=g_V3, out=g_u2
// pass 1: A=g_A1, B=g_B0, scale=g_u2, out=g_u1
// out[a, n] = sum_b C[a*32+b, n] * scale[b, n],  a = mt*4 + wm.
// ---------------------------------------------------------------------------
__global__ __launch_bounds__(256, 2)
void tt_gemm_kernel(int pass)
{
    const uint32_t* __restrict__ Apk   = (pass == 0) ? g_A2 : g_A1;
    const uint32_t* __restrict__ Bpk   = (pass == 0) ? g_B1 : g_B0;
    const float*    __restrict__ scale = (pass == 0) ? g_V3 : g_u2;
    float*          __restrict__ out   = (pass == 0) ? g_u2 : g_u1;

    extern __shared__ char smem[];
    const int t = threadIdx.x, warp = t >> 5, lane = t & 31;
    const int wm = warp & 3, wn = warp >> 2;
    const int g = lane >> 2, c = lane & 3;
    const int nt = blockIdx.x, mt = blockIdx.y;
    const uint32_t sbase = smem_u32(smem);

    // ldmatrix per-lane row geometry (loop-invariant)
    const int mat  = lane >> 3;          // 0..3
    const int mrow = lane & 7;
    // A: mat&1 -> +8 rows, mat>>1 -> k-half
    const int hA = mat >> 1;
    const int rA0 = (wm * 2 + 0) * 16 + (mat & 1) * 8 + mrow;   // i=0 row
    const int rA1 = rA0 + 16;                                    // i=1 row
    // B: mat>>1 -> +8 n-rows (next j), mat&1 -> k-half
    const int hB = mat & 1;
    const int rB = wn * 64 + (mat >> 1) * 8 + mrow;              // + jp*8

    float* sS = (float*)(smem + SM_SCALE);
#pragma unroll
    for (int i = 0; i < 16; i++) {
        int idx = t + i * 256;
        sS[(idx >> 7) * 132 + (idx & 127)] = scale[(idx >> 7) * NB + nt * 128 + (idx & 127)];
    }

    const uint32_t* Asrc = Apk + mt * 65536;   // 16 kc * 4096
    const uint32_t* Bsrc = Bpk + nt * 65536;

    float acc[2][8][4];
#pragma unroll
    for (int i = 0; i < 2; i++)
#pragma unroll
        for (int j = 0; j < 8; j++)
#pragma unroll
            for (int q = 0; q < 4; q++) acc[i][j][q] = 0.f;

    // prologue: stage 0 <- kc 0 (A 4096 w | B 4096 w = 32 KB)
    {
        uint32_t sd = sbase + SM_ST;
        const uint4* a4 = (const uint4*)(Asrc);
        const uint4* b4 = (const uint4*)(Bsrc);
#pragma unroll
        for (int j = 0; j < 4; j++) cp16(sd + (t + j * 256) * 16, a4 + t + j * 256);
#pragma unroll
        for (int j = 0; j < 4; j++) cp16(sd + 16384 + (t + j * 256) * 16, b4 + t + j * 256);
        CP_COMMIT();
    }

    for (int kc = 0; kc < 16; kc++) {
        if (kc > 0) __syncthreads();         // prior compute done before refill
        if (kc < 15) {
            uint32_t sd = sbase + SM_ST + ((kc + 1) & 1) * 32768;
            const uint4* a4 = (const uint4*)(Asrc + (kc + 1) * 4096);
            const uint4* b4 = (const uint4*)(Bsrc + (kc + 1) * 4096);
#pragma unroll
            for (int j = 0; j < 4; j++) cp16(sd + (t + j * 256) * 16, a4 + t + j * 256);
#pragma unroll
            for (int j = 0; j < 4; j++) cp16(sd + 16384 + (t + j * 256) * 16, b4 + t + j * 256);
            CP_COMMIT();
            asm volatile("cp.async.wait_group 1;" ::: "memory");
        } else {
            asm volatile("cp.async.wait_group 0;" ::: "memory");
        }
        __syncthreads();

        const uint32_t sA = sbase + SM_ST + (kc & 1) * 32768;
        const uint32_t sB = sA + 16384;

#pragma unroll
        for (int ks = 0; ks < 2; ks++) {
            // A fragments: hi/lo for i=0,1
            uint32_t ah[2][4], al[2][4];
            {
                uint32_t kgA = (uint32_t)((ks * 2 + hA));
                uint32_t w0 = rA0 * 16 + ((kgA ^ (rA0 & 3)) << 2);
                uint32_t w1 = rA1 * 16 + ((kgA ^ (rA1 & 3)) << 2);
                ldsm4(ah[0], sA + w0 * 4);
                ldsm4(ah[1], sA + w1 * 4);
                ldsm4(al[0], sA + (2048 + w0) * 4);
                ldsm4(al[1], sA + (2048 + w1) * 4);
            }
#pragma unroll
            for (int jp = 0; jp < 8; jp += 2) {
                uint32_t bh[4], bl[4];   // [j][0..1], [j+1][0..1]
                {
                    int rn = rB + jp * 8;
                    uint32_t kgB = (uint32_t)(ks * 2 + hB);
                    uint32_t w = rn * 16 + ((kgB ^ (rn & 3)) << 2);
                    ldsm4(bh, sB + w * 4);
                    ldsm4(bl, sB + (2048 + w) * 4);
                }
#pragma unroll
                for (int i = 0; i < 2; i++) {
                    mma16816(acc[i][jp],     ah[i], bh);
                    mma16816(acc[i][jp + 1], ah[i], bh + 2);
                    mma16816(acc[i][jp],     ah[i], bl);
                    mma16816(acc[i][jp + 1], ah[i], bl + 2);
                    mma16816(acc[i][jp],     al[i], bh);
                    mma16816(acc[i][jp + 1], al[i], bh + 2);
                }
            }
        }
    }

    // epilogue: contract over b = rows of the warp's 32-row strip
    const int a = mt * 4 + wm;
    float* dst = out + a * NB + nt * 128 + wn * 64;
#pragma unroll
    for (int j = 0; j < 8; j++) {
        int col0 = wn * 64 + j * 8 + c * 2;
        float p0 = 0.f, p1 = 0.f;
#pragma unroll
        for (int i = 0; i < 2; i++) {
            int b0 = i * 16 + g, b1 = b0 + 8;
            p0 += acc[i][j][0] * sS[b0 * 132 + col0] + acc[i][j][2] * sS[b1 * 132 + col0];
            p1 += acc[i][j][1] * sS[b0 * 132 + col0 + 1] + acc[i][j][3] * sS[b1 * 132 + col0 + 1];
        }
#pragma unroll
        for (int off = 4; off <= 16; off <<= 1) {
            p0 += __shfl_xor_sync(0xffffffffu, p0, off);
            p1 += __shfl_xor_sync(0xffffffffu, p1, off);
        }
        if (g == 0)
            *(float2*)&dst[j * 8 + c * 2] = make_float2(p0, p1);
    }
}

// ---------------------------------------------------------------------------
// Z[o,n] = sum_a core0[o*32+a] * u1[a,n]   (reads g_u1 directly)
// ---------------------------------------------------------------------------
__global__ __launch_bounds__(256)
void z_kernel(const float* __restrict__ core0, float* __restrict__ Z)
{
    __shared__ float cs[64 * 32];
    __shared__ float u1s[32][133];
    const int t = threadIdx.x, nt = blockIdx.x, og = blockIdx.y;
    const int n0 = nt * 128;
#pragma unroll
    for (int i = 0; i < 8; i++)
        cs[i * 256 + t] = core0[og * 64 * 32 + i * 256 + t];
#pragma unroll
    for (int i = 0; i < 16; i++) {
        int idx = t + i * 256;
        u1s[idx >> 7][idx & 127] = g_u1[(idx >> 7) * NB + n0 + (idx & 127)];
    }
    __syncthreads();
    const int j = t & 127, to = t >> 7;
    float u1r[32];
#pragma unroll
    for (int a = 0; a < 32; a++) u1r[a] = u1s[a][j];
#pragma unroll 4
    for (int oo = 0; oo < 32; oo++) {
        int ol = to * 32 + oo;
        float acc = 0.f;
#pragma unroll
        for (int a = 0; a < 32; a++)
            acc += cs[ol * 32 + a] * u1r[a];
        Z[(og * 64 + ol) * NB + n0 + j] = acc;
    }
}

// ---------------------------------------------------------------------------
extern "C" void kernel_launch(void* const* d_in, const int* in_sizes, int n_in,
                              void* d_out, int out_size)
{
    const float* X0    = (const float*)d_in[0];
    const float* X1    = (const float*)d_in[1];
    const float* X2    = (const float*)d_in[2];
    const float* core0 = (const float*)d_in[3];
    const float* core1 = (const float*)d_in[4];
    const float* core2 = (const float*)d_in[5];
    const float* core3 = (const float*)d_in[6];
    float* Z = (float*)d_out;

    static bool attr_done = false;
    if (!attr_done) {
        cudaFuncSetAttribute(tt_gemm_kernel,
                             cudaFuncAttributeMaxDynamicSharedMemorySize, SM_TOTAL);
        attr_done = true;
    }

    pack_core_kernel<<<dim3(8, 16), 256>>>(core1, 1);
    pack_core_kernel<<<dim3(8, 16), 256>>>(core2, 2);
    pack_x_kernel<<<dim3(32, 16), 256>>>(X0, 0);
    pack_x_kernel<<<dim3(32, 16), 256>>>(X1, 1);
    v3_kernel<<<32, 256>>>(core3, X2);
    tt_gemm_kernel<<<dim3(32, 8), 256, SM_TOTAL>>>(0);  // core2 x X1, scale v3 -> u2
    tt_gemm_kernel<<<dim3(32, 8), 256, SM_TOTAL>>>(1);  // core1 x X0, scale u2 -> u1
    z_kernel<<<dim3(32, 8), 256>>>(core0, Z);
}

// round 8
// speedup vs baseline: 2.4174x; 1.1798x over previous
#include <cuda_runtime.h>
#include <cuda_fp16.h>
#include <cstdint>

// ============================================================================
// TensorTrain forward via mma.sync (fp16, A-split 2-term) + fused contraction.
//   v3 = core3 @ X2                                   [32,4096]
//   GEMM pass0: perm(core2)@X1 tiles, epi * v3 -> u2  [32,4096]
//   GEMM pass1: perm(core1)@X0 tiles, epi * u2 -> u1  [32,4096]
//   Z = core0 @ u1                                    [512,4096]
//
// A (cores, pre-scaled x64) packed as TWO fp16 splits: Ah = fl16(64x),
// Al = fl16(64x - Ah)  ->  A exact. B (X) packed as ONE fp16 (2^-11 rounding).
// D = Ah*B + Al*B accumulated in f32; epilogue multiplies by 1/64.
//
// Packed word layout per (tile, kc=32k) block:
//   A block 4096 w: word[split*2048 + row*16 + (kp ^ ((row&3)<<2))]
//   B block 2048 w: word[            row*16 + (kp ^ ((row&3)<<2))]
//   word = f16pair(M[row][2kp], M[row][2kp+1]); 16B groups stay contiguous
//   (XOR touches bits >=2 only) -> ldmatrix-able, conflict-free.
// __device__ globals are ONLY referenced from device code (selected by flag).
// ============================================================================

namespace {
constexpr int NB = 4096;
constexpr int D  = 512;
constexpr int R  = 32;
constexpr float ASCALE   = 64.f;
constexpr float UNSCALE  = 1.f / 64.f;
constexpr int SM_SCALE = 0;        // sS: 32 x 132 f32 = 16896 B
constexpr int SM_ST    = 17408;    // two 24 KB stages (A 16K | B 8K each)
constexpr int STAGE_B  = 24576;
constexpr int SM_TOTAL = SM_ST + 2 * STAGE_B;   // 66560 -> 2 CTAs/SM
}

__device__ float g_V3[R * NB];
__device__ float g_u2[R * NB];
__device__ float g_u1[R * NB];
// A blocks: [mt(8)][kc(16)] x 4096 words ; B blocks: [nt(32)][kc(16)] x 2048 words
__device__ uint32_t g_A1[8 * 16 * 4096];
__device__ uint32_t g_A2[8 * 16 * 4096];
__device__ uint32_t g_B0[32 * 16 * 2048];
__device__ uint32_t g_B1[32 * 16 * 2048];

// ---------------------------------------------------------------------------
__device__ __forceinline__ uint32_t smem_u32(const void* p) {
    uint32_t a;
    asm("{ .reg .u64 t; cvta.to.shared.u64 t, %1; cvt.u32.u64 %0, t; }" : "=r"(a) : "l"(p));
    return a;
}
__device__ __forceinline__ void cp16(uint32_t saddr, const void* g) {
    asm volatile("cp.async.cg.shared.global [%0], [%1], 16;" :: "r"(saddr), "l"(g) : "memory");
}
#define CP_COMMIT() asm volatile("cp.async.commit_group;" ::: "memory")

__device__ __forceinline__ void mma16816(float* d, const uint32_t* a, const uint32_t* b) {
    asm volatile(
        "mma.sync.aligned.m16n8k16.row.col.f32.f16.f16.f32 "
        "{%0,%1,%2,%3}, {%4,%5,%6,%7}, {%8,%9}, {%0,%1,%2,%3};"
        : "+f"(d[0]), "+f"(d[1]), "+f"(d[2]), "+f"(d[3])
        : "r"(a[0]), "r"(a[1]), "r"(a[2]), "r"(a[3]), "r"(b[0]), "r"(b[1]));
}
__device__ __forceinline__ void ldsm4(uint32_t* r, uint32_t saddr) {
    asm volatile("ldmatrix.sync.aligned.m8n8.x4.shared.b16 {%0,%1,%2,%3}, [%4];"
                 : "=r"(r[0]), "=r"(r[1]), "=r"(r[2]), "=r"(r[3]) : "r"(saddr));
}
__device__ __forceinline__ uint32_t h2pack(__half a, __half b) {
    return ((uint32_t)__half_as_ushort(b) << 16) | __half_as_ushort(a);
}
// A split (scaled x64): split0 = hi, split1 = residual
__device__ __forceinline__ uint32_t pack_a(float x0, float x1, int split) {
    float y0 = x0 * ASCALE, y1 = x1 * ASCALE;
    __half h0 = __float2half_rn(y0), h1 = __float2half_rn(y1);
    if (split == 0) return h2pack(h0, h1);
    __half l0 = __float2half_rn(y0 - __half2float(h0));
    __half l1 = __float2half_rn(y1 - __half2float(h1));
    return h2pack(l0, l1);
}
__device__ __forceinline__ uint32_t pack_b(float x0, float x1) {
    return h2pack(__float2half_rn(x0), __float2half_rn(x1));
}

// ---------------------------------------------------------------------------
// Pack core[a,k,b] (32x512x32 f32) -> A blocks. grid (mt=8, kc=16), 256 thr.
// which: 1 -> g_A1, 2 -> g_A2.  Block: rows m=mt*128..+127, k=kc*32..+31.
// ---------------------------------------------------------------------------
__global__ __launch_bounds__(256)
void pack_core_kernel(const float* __restrict__ core, int which)
{
    uint32_t* __restrict__ out = (which == 1) ? g_A1 : g_A2;
    __shared__ float sC[4 * 1056];    // [a_loc][kloc(32) stride 33][b(32)]
    const int t = threadIdx.x, mt = blockIdx.x, kc = blockIdx.y;
#pragma unroll
    for (int i = 0; i < 16; i++) {
        int idx = t + i * 256;                 // 0..4095
        int a_loc = idx >> 10, rem = idx & 1023;
        int kloc = rem >> 5, b = rem & 31;
        sC[a_loc * 1056 + kloc * 33 + b] =
            core[(mt * 4 + a_loc) * (D * R) + kc * 1024 + rem];
    }
    __syncthreads();
    uint32_t* dst = out + (mt * 16 + kc) * 4096;
#pragma unroll
    for (int i = 0; i < 16; i++) {
        int w = t + i * 256;
        int split = w >> 11, rem = w & 2047;
        int m_loc = rem >> 4, wsw = rem & 15;
        int kp = wsw ^ ((m_loc & 3) << 2);
        int a_loc = m_loc >> 5, b = m_loc & 31, k0 = kp * 2;
        float x0 = sC[a_loc * 1056 + k0 * 33 + b];
        float x1 = sC[a_loc * 1056 + (k0 + 1) * 33 + b];
        dst[w] = pack_a(x0, x1, split);
    }
}

// ---------------------------------------------------------------------------
// Pack X[k,n] (512x4096 f32) -> B blocks (single fp16). grid (nt=32, kc=16).
// which: 0 -> g_B0, 1 -> g_B1.
// ---------------------------------------------------------------------------
__global__ __launch_bounds__(256)
void pack_x_kernel(const float* __restrict__ X, int which)
{
    uint32_t* __restrict__ out = (which == 0) ? g_B0 : g_B1;
    __shared__ float sX[32 * 129];
    const int t = threadIdx.x, nt = blockIdx.x, kc = blockIdx.y;
#pragma unroll
    for (int i = 0; i < 16; i++) {
        int idx = t + i * 256;
        int k = idx >> 7, nl = idx & 127;
        sX[k * 129 + nl] = X[(kc * 32 + k) * NB + nt * 128 + nl];
    }
    __syncthreads();
    uint32_t* dst = out + (nt * 16 + kc) * 2048;
#pragma unroll
    for (int i = 0; i < 8; i++) {
        int w = t + i * 256;                   // 0..2047
        int n_loc = w >> 4, wsw = w & 15;
        int kp = wsw ^ ((n_loc & 3) << 2);
        int k0 = kp * 2;
        dst[w] = pack_b(sX[k0 * 129 + n_loc], sX[(k0 + 1) * 129 + n_loc]);
    }
}

// ---------------------------------------------------------------------------
// v3[a,n] = sum_d core3[a,d] * X2[d,n]   (writes g_V3 directly)
// ---------------------------------------------------------------------------
__global__ __launch_bounds__(256)
void v3_kernel(const float* __restrict__ core3, const float* __restrict__ X2)
{
    __shared__ float Xs[32][128];
    const int t = threadIdx.x, n0 = blockIdx.x * 128;
    const int nl = t & 127, ab = (t >> 7) * 16;
    float acc[16];
#pragma unroll
    for (int i = 0; i < 16; i++) acc[i] = 0.f;
    for (int d0 = 0; d0 < D; d0 += 32) {
#pragma unroll
        for (int i = 0; i < 16; i++) {
            int idx = t + i * 256;
            Xs[idx >> 7][idx & 127] = X2[(d0 + (idx >> 7)) * NB + n0 + (idx & 127)];
        }
        __syncthreads();
#pragma unroll
        for (int dl = 0; dl < 32; dl++) {
            float x = Xs[dl][nl];
#pragma unroll
            for (int i = 0; i < 16; i++)
                acc[i] += core3[(ab + i) * D + d0 + dl] * x;
        }
        __syncthreads();
    }
#pragma unroll
    for (int i = 0; i < 16; i++)
        g_V3[(ab + i) * NB + n0 + nl] = acc[i];
}

// ---------------------------------------------------------------------------
// Tensor GEMM (fp16 A-split 2-term, ldmatrix) + fused contraction epilogue.
// grid (nt=32, mt=8), 256 thr, 2 CTAs/SM. warp wm=warp&3 (M32), wn=warp>>2 (N64).
// pass 0: A=g_A2, B=g_B1, scale=g_V3, out=g_u2
// pass 1: A=g_A1, B=g_B0, scale=g_u2, out=g_u1
// out[a, n] = (1/64) * sum_b C[a*32+b, n] * scale[b, n],  a = mt*4 + wm.
// ---------------------------------------------------------------------------
__global__ __launch_bounds__(256, 2)
void tt_gemm_kernel(int pass)
{
    const uint32_t* __restrict__ Apk   = (pass == 0) ? g_A2 : g_A1;
    const uint32_t* __restrict__ Bpk   = (pass == 0) ? g_B1 : g_B0;
    const float*    __restrict__ scale = (pass == 0) ? g_V3 : g_u2;
    float*          __restrict__ out   = (pass == 0) ? g_u2 : g_u1;

    extern __shared__ char smem[];
    const int t = threadIdx.x, warp = t >> 5, lane = t & 31;
    const int wm = warp & 3, wn = warp >> 2;
    const int g = lane >> 2, c = lane & 3;
    const int nt = blockIdx.x, mt = blockIdx.y;
    const uint32_t sbase = smem_u32(smem);

    // ldmatrix per-lane row geometry (loop-invariant)
    const int mat  = lane >> 3;          // 0..3
    const int mrow = lane & 7;
    const int hA = mat >> 1;                                     // A k-half
    const int rA0 = (wm * 2 + 0) * 16 + (mat & 1) * 8 + mrow;    // i=0 row
    const int rA1 = rA0 + 16;                                    // i=1 row
    const int hB = mat & 1;                                      // B k-half
    const int rB = wn * 64 + (mat >> 1) * 8 + mrow;              // + jp*8

    float* sS = (float*)(smem + SM_SCALE);
#pragma unroll
    for (int i = 0; i < 16; i++) {
        int idx = t + i * 256;
        sS[(idx >> 7) * 132 + (idx & 127)] = scale[(idx >> 7) * NB + nt * 128 + (idx & 127)];
    }

    const uint32_t* Asrc = Apk + mt * 65536;   // 16 kc * 4096
    const uint32_t* Bsrc = Bpk + nt * 32768;   // 16 kc * 2048

    float acc[2][8][4];
#pragma unroll
    for (int i = 0; i < 2; i++)
#pragma unroll
        for (int j = 0; j < 8; j++)
#pragma unroll
            for (int q = 0; q < 4; q++) acc[i][j][q] = 0.f;

    // prologue: stage 0 <- kc 0 (A 4096 w | B 2048 w = 24 KB)
    {
        uint32_t sd = sbase + SM_ST;
        const uint4* a4 = (const uint4*)(Asrc);
        const uint4* b4 = (const uint4*)(Bsrc);
#pragma unroll
        for (int j = 0; j < 4; j++) cp16(sd + (t + j * 256) * 16, a4 + t + j * 256);
#pragma unroll
        for (int j = 0; j < 2; j++) cp16(sd + 16384 + (t + j * 256) * 16, b4 + t + j * 256);
        CP_COMMIT();
    }

    for (int kc = 0; kc < 16; kc++) {
        if (kc > 0) __syncthreads();         // prior compute done before refill
        if (kc < 15) {
            uint32_t sd = sbase + SM_ST + ((kc + 1) & 1) * STAGE_B;
            const uint4* a4 = (const uint4*)(Asrc + (kc + 1) * 4096);
            const uint4* b4 = (const uint4*)(Bsrc + (kc + 1) * 2048);
#pragma unroll
            for (int j = 0; j < 4; j++) cp16(sd + (t + j * 256) * 16, a4 + t + j * 256);
#pragma unroll
            for (int j = 0; j < 2; j++) cp16(sd + 16384 + (t + j * 256) * 16, b4 + t + j * 256);
            CP_COMMIT();
            asm volatile("cp.async.wait_group 1;" ::: "memory");
        } else {
            asm volatile("cp.async.wait_group 0;" ::: "memory");
        }
        __syncthreads();

        const uint32_t sA = sbase + SM_ST + (kc & 1) * STAGE_B;
        const uint32_t sB = sA + 16384;

#pragma unroll
        for (int ks = 0; ks < 2; ks++) {
            // A fragments: hi (split0) / lo (split1) for i = 0,1
            uint32_t ah[2][4], al[2][4];
            {
                uint32_t kgA = (uint32_t)(ks * 2 + hA);
                uint32_t w0 = rA0 * 16 + ((kgA ^ (rA0 & 3)) << 2);
                uint32_t w1 = rA1 * 16 + ((kgA ^ (rA1 & 3)) << 2);
                ldsm4(ah[0], sA + w0 * 4);
                ldsm4(ah[1], sA + w1 * 4);
                ldsm4(al[0], sA + (2048 + w0) * 4);
                ldsm4(al[1], sA + (2048 + w1) * 4);
            }
#pragma unroll
            for (int jp = 0; jp < 8; jp += 2) {
                uint32_t bb[4];   // [j][0..1], [j+1][0..1]
                {
                    int rn = rB + jp * 8;
                    uint32_t kgB = (uint32_t)(ks * 2 + hB);
                    uint32_t w = rn * 16 + ((kgB ^ (rn & 3)) << 2);
                    ldsm4(bb, sB + w * 4);
                }
#pragma unroll
                for (int i = 0; i < 2; i++) {
                    mma16816(acc[i][jp],     ah[i], bb);
                    mma16816(acc[i][jp + 1], ah[i], bb + 2);
                    mma16816(acc[i][jp],     al[i], bb);
                    mma16816(acc[i][jp + 1], al[i], bb + 2);
                }
            }
        }
    }

    // epilogue: contract over b = rows of the warp's 32-row strip, unscale
    const int a = mt * 4 + wm;
    float* dst = out + a * NB + nt * 128 + wn * 64;
#pragma unroll
    for (int j = 0; j < 8; j++) {
        int col0 = wn * 64 + j * 8 + c * 2;
        float p0 = 0.f, p1 = 0.f;
#pragma unroll
        for (int i = 0; i < 2; i++) {
            int b0 = i * 16 + g, b1 = b0 + 8;
            p0 += acc[i][j][0] * sS[b0 * 132 + col0] + acc[i][j][2] * sS[b1 * 132 + col0];
            p1 += acc[i][j][1] * sS[b0 * 132 + col0 + 1] + acc[i][j][3] * sS[b1 * 132 + col0 + 1];
        }
#pragma unroll
        for (int off = 4; off <= 16; off <<= 1) {
            p0 += __shfl_xor_sync(0xffffffffu, p0, off);
            p1 += __shfl_xor_sync(0xffffffffu, p1, off);
        }
        if (g == 0)
            *(float2*)&dst[j * 8 + c * 2] = make_float2(p0 * UNSCALE, p1 * UNSCALE);
    }
}

// ---------------------------------------------------------------------------
// Z[o,n] = sum_a core0[o*32+a] * u1[a,n]   (reads g_u1 directly)
// ---------------------------------------------------------------------------
__global__ __launch_bounds__(256)
void z_kernel(const float* __restrict__ core0, float* __restrict__ Z)
{
    __shared__ float cs[64 * 32];
    __shared__ float u1s[32][133];
    const int t = threadIdx.x, nt = blockIdx.x, og = blockIdx.y;
    const int n0 = nt * 128;
#pragma unroll
    for (int i = 0; i < 8; i++)
        cs[i * 256 + t] = core0[og * 64 * 32 + i * 256 + t];
#pragma unroll
    for (int i = 0; i < 16; i++) {
        int idx = t + i * 256;
        u1s[idx >> 7][idx & 127] = g_u1[(idx >> 7) * NB + n0 + (idx & 127)];
    }
    __syncthreads();
    const int j = t & 127, to = t >> 7;
    float u1r[32];
#pragma unroll
    for (int a = 0; a < 32; a++) u1r[a] = u1s[a][j];
#pragma unroll 4
    for (int oo = 0; oo < 32; oo++) {
        int ol = to * 32 + oo;
        float acc = 0.f;
#pragma unroll
        for (int a = 0; a < 32; a++)
            acc += cs[ol * 32 + a] * u1r[a];
        Z[(og * 64 + ol) * NB + n0 + j] = acc;
    }
}

// ---------------------------------------------------------------------------
extern "C" void kernel_launch(void* const* d_in, const int* in_sizes, int n_in,
                              void* d_out, int out_size)
{
    const float* X0    = (const float*)d_in[0];
    const float* X1    = (const float*)d_in[1];
    const float* X2    = (const float*)d_in[2];
    const float* core0 = (const float*)d_in[3];
    const float* core1 = (const float*)d_in[4];
    const float* core2 = (const float*)d_in[5];
    const float* core3 = (const float*)d_in[6];
    float* Z = (float*)d_out;

    static bool attr_done = false;
    if (!attr_done) {
        cudaFuncSetAttribute(tt_gemm_kernel,
                             cudaFuncAttributeMaxDynamicSharedMemorySize, SM_TOTAL);
        attr_done = true;
    }

    pack_core_kernel<<<dim3(8, 16), 256>>>(core1, 1);
    pack_core_kernel<<<dim3(8, 16), 256>>>(core2, 2);
    pack_x_kernel<<<dim3(32, 16), 256>>>(X0, 0);
    pack_x_kernel<<<dim3(32, 16), 256>>>(X1, 1);
    v3_kernel<<<32, 256>>>(core3, X2);
    tt_gemm_kernel<<<dim3(32, 8), 256, SM_TOTAL>>>(0);  // core2 x X1, scale v3 -> u2
    tt_gemm_kernel<<<dim3(32, 8), 256, SM_TOTAL>>>(1);  // core1 x X0, scale u2 -> u1
    z_kernel<<<dim3(32, 8), 256>>>(core0, Z);
}

// round 9
// speedup vs baseline: 2.7240x; 1.1268x over previous
#include <cuda_runtime.h>
#include <cuda_fp16.h>
#include <cstdint>

// ============================================================================
// TensorTrain forward via mma.sync (single fp16 term) + fused rank contraction.
//   v3 = core3 @ X2                                   [32,4096]
//   GEMM pass0: perm(core2)@X1 tiles, epi * v3 -> u2  [32,4096]
//   GEMM pass1: perm(core1)@X0 tiles, epi * u2 -> u1  [32,4096]
//   Z = core0 @ u1                                    [512,4096]
//
// A (cores) pre-scaled x64 and rounded to fp16; B (X) rounded to fp16.
// D = A*B accumulated in f32; epilogue multiplies by 1/64.
// Measured error with B-only rounding was 2.94e-4; A rounding adds in
// quadrature -> predicted ~5e-4 vs 1e-3 threshold.
//
// Packed word layout per (tile, kc=32k) block of 2048 u32 words:
//   word[row*16 + (kp ^ ((row&3)<<2))] = f16pair(M[row][2kp], M[row][2kp+1])
//   16B groups stay contiguous (XOR touches bits >=2 only) -> ldmatrix-able,
//   8 rows of each 8x8 matrix land on distinct bank groups.
// __device__ globals are ONLY referenced from device code (selected by flag).
// ============================================================================

namespace {
constexpr int NB = 4096;
constexpr int D  = 512;
constexpr int R  = 32;
constexpr float ASCALE  = 64.f;
constexpr float UNSCALE = 1.f / 64.f;
constexpr int SM_SCALE = 0;        // sS: 32 x 132 f32 = 16896 B
constexpr int SM_ST    = 17408;    // two 16 KB stages (A 8K | B 8K each)
constexpr int STAGE_B  = 16384;
constexpr int SM_TOTAL = SM_ST + 2 * STAGE_B;   // 50176
}

__device__ float g_V3[R * NB];
__device__ float g_u2[R * NB];
__device__ float g_u1[R * NB];
// A blocks: [mt(8)][kc(16)] x 2048 words ; B blocks: [nt(32)][kc(16)] x 2048 words
__device__ uint32_t g_A1[8 * 16 * 2048];
__device__ uint32_t g_A2[8 * 16 * 2048];
__device__ uint32_t g_B0[32 * 16 * 2048];
__device__ uint32_t g_B1[32 * 16 * 2048];

// ---------------------------------------------------------------------------
__device__ __forceinline__ uint32_t smem_u32(const void* p) {
    uint32_t a;
    asm("{ .reg .u64 t; cvta.to.shared.u64 t, %1; cvt.u32.u64 %0, t; }" : "=r"(a) : "l"(p));
    return a;
}
__device__ __forceinline__ void cp16(uint32_t saddr, const void* g) {
    asm volatile("cp.async.cg.shared.global [%0], [%1], 16;" :: "r"(saddr), "l"(g) : "memory");
}
#define CP_COMMIT() asm volatile("cp.async.commit_group;" ::: "memory")

__device__ __forceinline__ void mma16816(float* d, const uint32_t* a, const uint32_t* b) {
    asm volatile(
        "mma.sync.aligned.m16n8k16.row.col.f32.f16.f16.f32 "
        "{%0,%1,%2,%3}, {%4,%5,%6,%7}, {%8,%9}, {%0,%1,%2,%3};"
        : "+f"(d[0]), "+f"(d[1]), "+f"(d[2]), "+f"(d[3])
        : "r"(a[0]), "r"(a[1]), "r"(a[2]), "r"(a[3]), "r"(b[0]), "r"(b[1]));
}
__device__ __forceinline__ void ldsm4(uint32_t* r, uint32_t saddr) {
    asm volatile("ldmatrix.sync.aligned.m8n8.x4.shared.b16 {%0,%1,%2,%3}, [%4];"
                 : "=r"(r[0]), "=r"(r[1]), "=r"(r[2]), "=r"(r[3]) : "r"(saddr));
}
__device__ __forceinline__ uint32_t h2pack(__half a, __half b) {
    return ((uint32_t)__half_as_ushort(b) << 16) | __half_as_ushort(a);
}
__device__ __forceinline__ uint32_t pack_a(float x0, float x1) {
    return h2pack(__float2half_rn(x0 * ASCALE), __float2half_rn(x1 * ASCALE));
}
__device__ __forceinline__ uint32_t pack_b(float x0, float x1) {
    return h2pack(__float2half_rn(x0), __float2half_rn(x1));
}

// ---------------------------------------------------------------------------
// Pack core[a,k,b] (32x512x32 f32) -> A blocks. grid (mt=8, kc=16), 256 thr.
// which: 1 -> g_A1, 2 -> g_A2.  Block: rows m=mt*128..+127, k=kc*32..+31.
// ---------------------------------------------------------------------------
__global__ __launch_bounds__(256)
void pack_core_kernel(const float* __restrict__ core, int which)
{
    uint32_t* __restrict__ out = (which == 1) ? g_A1 : g_A2;
    __shared__ float sC[4 * 1056];    // [a_loc][kloc(32) stride 33][b(32)]
    const int t = threadIdx.x, mt = blockIdx.x, kc = blockIdx.y;
#pragma unroll
    for (int i = 0; i < 16; i++) {
        int idx = t + i * 256;                 // 0..4095
        int a_loc = idx >> 10, rem = idx & 1023;
        int kloc = rem >> 5, b = rem & 31;
        sC[a_loc * 1056 + kloc * 33 + b] =
            core[(mt * 4 + a_loc) * (D * R) + kc * 1024 + rem];
    }
    __syncthreads();
    uint32_t* dst = out + (mt * 16 + kc) * 2048;
#pragma unroll
    for (int i = 0; i < 8; i++) {
        int w = t + i * 256;                   // 0..2047
        int m_loc = w >> 4, wsw = w & 15;
        int kp = wsw ^ ((m_loc & 3) << 2);
        int a_loc = m_loc >> 5, b = m_loc & 31, k0 = kp * 2;
        float x0 = sC[a_loc * 1056 + k0 * 33 + b];
        float x1 = sC[a_loc * 1056 + (k0 + 1) * 33 + b];
        dst[w] = pack_a(x0, x1);
    }
}

// ---------------------------------------------------------------------------
// Pack X[k,n] (512x4096 f32) -> B blocks (single fp16). grid (nt=32, kc=16).
// which: 0 -> g_B0, 1 -> g_B1.
// ---------------------------------------------------------------------------
__global__ __launch_bounds__(256)
void pack_x_kernel(const float* __restrict__ X, int which)
{
    uint32_t* __restrict__ out = (which == 0) ? g_B0 : g_B1;
    __shared__ float sX[32 * 129];
    const int t = threadIdx.x, nt = blockIdx.x, kc = blockIdx.y;
#pragma unroll
    for (int i = 0; i < 16; i++) {
        int idx = t + i * 256;
        int k = idx >> 7, nl = idx & 127;
        sX[k * 129 + nl] = X[(kc * 32 + k) * NB + nt * 128 + nl];
    }
    __syncthreads();
    uint32_t* dst = out + (nt * 16 + kc) * 2048;
#pragma unroll
    for (int i = 0; i < 8; i++) {
        int w = t + i * 256;                   // 0..2047
        int n_loc = w >> 4, wsw = w & 15;
        int kp = wsw ^ ((n_loc & 3) << 2);
        int k0 = kp * 2;
        dst[w] = pack_b(sX[k0 * 129 + n_loc], sX[(k0 + 1) * 129 + n_loc]);
    }
}

// ---------------------------------------------------------------------------
// v3[a,n] = sum_d core3[a,d] * X2[d,n]   (writes g_V3 directly)
// ---------------------------------------------------------------------------
__global__ __launch_bounds__(256)
void v3_kernel(const float* __restrict__ core3, const float* __restrict__ X2)
{
    __shared__ float Xs[32][128];
    const int t = threadIdx.x, n0 = blockIdx.x * 128;
    const int nl = t & 127, ab = (t >> 7) * 16;
    float acc[16];
#pragma unroll
    for (int i = 0; i < 16; i++) acc[i] = 0.f;
    for (int d0 = 0; d0 < D; d0 += 32) {
#pragma unroll
        for (int i = 0; i < 16; i++) {
            int idx = t + i * 256;
            Xs[idx >> 7][idx & 127] = X2[(d0 + (idx >> 7)) * NB + n0 + (idx & 127)];
        }
        __syncthreads();
#pragma unroll
        for (int dl = 0; dl < 32; dl++) {
            float x = Xs[dl][nl];
#pragma unroll
            for (int i = 0; i < 16; i++)
                acc[i] += core3[(ab + i) * D + d0 + dl] * x;
        }
        __syncthreads();
    }
#pragma unroll
    for (int i = 0; i < 16; i++)
        g_V3[(ab + i) * NB + n0 + nl] = acc[i];
}

// ---------------------------------------------------------------------------
// Tensor GEMM (single fp16 term, ldmatrix) + fused contraction epilogue.
// grid (nt=32, mt=8), 256 thr, 2 CTAs/SM. warp wm=warp&3 (M32), wn=warp>>2 (N64).
// pass 0: A=g_A2, B=g_B1, scale=g_V3, out=g_u2
// pass 1: A=g_A1, B=g_B0, scale=g_u2, out=g_u1
// out[a, n] = (1/64) * sum_b C[a*32+b, n] * scale[b, n],  a = mt*4 + wm.
// ---------------------------------------------------------------------------
__global__ __launch_bounds__(256, 2)
void tt_gemm_kernel(int pass)
{
    const uint32_t* __restrict__ Apk   = (pass == 0) ? g_A2 : g_A1;
    const uint32_t* __restrict__ Bpk   = (pass == 0) ? g_B1 : g_B0;
    const float*    __restrict__ scale = (pass == 0) ? g_V3 : g_u2;
    float*          __restrict__ out   = (pass == 0) ? g_u2 : g_u1;

    extern __shared__ char smem[];
    const int t = threadIdx.x, warp = t >> 5, lane = t & 31;
    const int wm = warp & 3, wn = warp >> 2;
    const int g = lane >> 2, c = lane & 3;
    const int nt = blockIdx.x, mt = blockIdx.y;
    const uint32_t sbase = smem_u32(smem);

    // ldmatrix per-lane row geometry (loop-invariant)
    const int mat  = lane >> 3;          // 0..3
    const int mrow = lane & 7;
    const int hA = mat >> 1;                                     // A k-half
    const int rA0 = (wm * 2 + 0) * 16 + (mat & 1) * 8 + mrow;    // i=0 row
    const int rA1 = rA0 + 16;                                    // i=1 row
    const int hB = mat & 1;                                      // B k-half
    const int rB = wn * 64 + (mat >> 1) * 8 + mrow;              // + jp*8

    float* sS = (float*)(smem + SM_SCALE);
#pragma unroll
    for (int i = 0; i < 16; i++) {
        int idx = t + i * 256;
        sS[(idx >> 7) * 132 + (idx & 127)] = scale[(idx >> 7) * NB + nt * 128 + (idx & 127)];
    }

    const uint32_t* Asrc = Apk + mt * 32768;   // 16 kc * 2048
    const uint32_t* Bsrc = Bpk + nt * 32768;   // 16 kc * 2048

    float acc[2][8][4];
#pragma unroll
    for (int i = 0; i < 2; i++)
#pragma unroll
        for (int j = 0; j < 8; j++)
#pragma unroll
            for (int q = 0; q < 4; q++) acc[i][j][q] = 0.f;

    // prologue: stage 0 <- kc 0 (A 2048 w | B 2048 w = 16 KB)
    {
        uint32_t sd = sbase + SM_ST;
        const uint4* a4 = (const uint4*)(Asrc);
        const uint4* b4 = (const uint4*)(Bsrc);
#pragma unroll
        for (int j = 0; j < 2; j++) cp16(sd + (t + j * 256) * 16, a4 + t + j * 256);
#pragma unroll
        for (int j = 0; j < 2; j++) cp16(sd + 8192 + (t + j * 256) * 16, b4 + t + j * 256);
        CP_COMMIT();
    }

    for (int kc = 0; kc < 16; kc++) {
        if (kc > 0) __syncthreads();         // prior compute done before refill
        if (kc < 15) {
            uint32_t sd = sbase + SM_ST + ((kc + 1) & 1) * STAGE_B;
            const uint4* a4 = (const uint4*)(Asrc + (kc + 1) * 2048);
            const uint4* b4 = (const uint4*)(Bsrc + (kc + 1) * 2048);
#pragma unroll
            for (int j = 0; j < 2; j++) cp16(sd + (t + j * 256) * 16, a4 + t + j * 256);
#pragma unroll
            for (int j = 0; j < 2; j++) cp16(sd + 8192 + (t + j * 256) * 16, b4 + t + j * 256);
            CP_COMMIT();
            asm volatile("cp.async.wait_group 1;" ::: "memory");
        } else {
            asm volatile("cp.async.wait_group 0;" ::: "memory");
        }
        __syncthreads();

        const uint32_t sA = sbase + SM_ST + (kc & 1) * STAGE_B;
        const uint32_t sB = sA + 8192;

#pragma unroll
        for (int ks = 0; ks < 2; ks++) {
            // A fragments for i = 0,1
            uint32_t ah[2][4];
            {
                uint32_t kgA = (uint32_t)(ks * 2 + hA);
                uint32_t w0 = rA0 * 16 + ((kgA ^ (rA0 & 3)) << 2);
                uint32_t w1 = rA1 * 16 + ((kgA ^ (rA1 & 3)) << 2);
                ldsm4(ah[0], sA + w0 * 4);
                ldsm4(ah[1], sA + w1 * 4);
            }
#pragma unroll
            for (int jp = 0; jp < 8; jp += 2) {
                uint32_t bb[4];   // [j][0..1], [j+1][0..1]
                {
                    int rn = rB + jp * 8;
                    uint32_t kgB = (uint32_t)(ks * 2 + hB);
                    uint32_t w = rn * 16 + ((kgB ^ (rn & 3)) << 2);
                    ldsm4(bb, sB + w * 4);
                }
#pragma unroll
                for (int i = 0; i < 2; i++) {
                    mma16816(acc[i][jp],     ah[i], bb);
                    mma16816(acc[i][jp + 1], ah[i], bb + 2);
                }
            }
        }
    }

    // epilogue: contract over b = rows of the warp's 32-row strip, unscale
    const int a = mt * 4 + wm;
    float* dst = out + a * NB + nt * 128 + wn * 64;
#pragma unroll
    for (int j = 0; j < 8; j++) {
        int col0 = wn * 64 + j * 8 + c * 2;
        float p0 = 0.f, p1 = 0.f;
#pragma unroll
        for (int i = 0; i < 2; i++) {
            int b0 = i * 16 + g, b1 = b0 + 8;
            p0 += acc[i][j][0] * sS[b0 * 132 + col0] + acc[i][j][2] * sS[b1 * 132 + col0];
            p1 += acc[i][j][1] * sS[b0 * 132 + col0 + 1] + acc[i][j][3] * sS[b1 * 132 + col0 + 1];
        }
#pragma unroll
        for (int off = 4; off <= 16; off <<= 1) {
            p0 += __shfl_xor_sync(0xffffffffu, p0, off);
            p1 += __shfl_xor_sync(0xffffffffu, p1, off);
        }
        if (g == 0)
            *(float2*)&dst[j * 8 + c * 2] = make_float2(p0 * UNSCALE, p1 * UNSCALE);
    }
}

// ---------------------------------------------------------------------------
// Z[o,n] = sum_a core0[o*32+a] * u1[a,n]   (reads g_u1 directly)
// ---------------------------------------------------------------------------
__global__ __launch_bounds__(256)
void z_kernel(const float* __restrict__ core0, float* __restrict__ Z)
{
    __shared__ float cs[64 * 32];
    __shared__ float u1s[32][133];
    const int t = threadIdx.x, nt = blockIdx.x, og = blockIdx.y;
    const int n0 = nt * 128;
#pragma unroll
    for (int i = 0; i < 8; i++)
        cs[i * 256 + t] = core0[og * 64 * 32 + i * 256 + t];
#pragma unroll
    for (int i = 0; i < 16; i++) {
        int idx = t + i * 256;
        u1s[idx >> 7][idx & 127] = g_u1[(idx >> 7) * NB + n0 + (idx & 127)];
    }
    __syncthreads();
    const int j = t & 127, to = t >> 7;
    float u1r[32];
#pragma unroll
    for (int a = 0; a < 32; a++) u1r[a] = u1s[a][j];
#pragma unroll 4
    for (int oo = 0; oo < 32; oo++) {
        int ol = to * 32 + oo;
        float acc = 0.f;
#pragma unroll
        for (int a = 0; a < 32; a++)
            acc += cs[ol * 32 + a] * u1r[a];
        Z[(og * 64 + ol) * NB + n0 + j] = acc;
    }
}

// ---------------------------------------------------------------------------
extern "C" void kernel_launch(void* const* d_in, const int* in_sizes, int n_in,
                              void* d_out, int out_size)
{
    const float* X0    = (const float*)d_in[0];
    const float* X1    = (const float*)d_in[1];
    const float* X2    = (const float*)d_in[2];
    const float* core0 = (const float*)d_in[3];
    const float* core1 = (const float*)d_in[4];
    const float* core2 = (const float*)d_in[5];
    const float* core3 = (const float*)d_in[6];
    float* Z = (float*)d_out;

    static bool attr_done = false;
    if (!attr_done) {
        cudaFuncSetAttribute(tt_gemm_kernel,
                             cudaFuncAttributeMaxDynamicSharedMemorySize, SM_TOTAL);
        attr_done = true;
    }

    pack_core_kernel<<<dim3(8, 16), 256>>>(core1, 1);
    pack_core_kernel<<<dim3(8, 16), 256>>>(core2, 2);
    pack_x_kernel<<<dim3(32, 16), 256>>>(X0, 0);
    pack_x_kernel<<<dim3(32, 16), 256>>>(X1, 1);
    v3_kernel<<<32, 256>>>(core3, X2);
    tt_gemm_kernel<<<dim3(32, 8), 256, SM_TOTAL>>>(0);  // core2 x X1, scale v3 -> u2
    tt_gemm_kernel<<<dim3(32, 8), 256, SM_TOTAL>>>(1);  // core1 x X0, scale u2 -> u1
    z_kernel<<<dim3(32, 8), 256>>>(core0, Z);
}

// round 10
// speedup vs baseline: 2.8109x; 1.0319x over previous
#include <cuda_runtime.h>
#include <cuda_fp16.h>
#include <cstdint>

// ============================================================================
// TensorTrain forward via mma.sync (single fp16 term) + fused rank contraction.
//   v3 = core3 @ X2                                   [32,4096]
//   GEMM pass0: perm(core2)@X1 tiles, epi * v3 -> u2  [32,4096]
//   GEMM pass1: perm(core1)@X0 tiles, epi * u2 -> u1  [32,4096]
//   Z = core0 @ u1                                    [512,4096]
//
// A (cores) pre-scaled x64, fp16; B (X) fp16. D = A*B (f32 accum), epi x 1/64.
// GEMM CTA tile: 128m x 256n, grid (16 nq, 8 mt) = 128 CTAs (one wave),
// 3-stage cp.async pipeline, one __syncthreads per k-chunk.
//
// Packed word layout per (tile, kc=32k) block of 2048 u32 words:
//   word[row*16 + (kp ^ ((row&3)<<2))] = f16pair(M[row][2kp], M[row][2kp+1])
// __device__ globals are ONLY referenced from device code (selected by flag).
// ============================================================================

namespace {
constexpr int NB = 4096;
constexpr int D  = 512;
constexpr int R  = 32;
constexpr float ASCALE  = 64.f;
constexpr float UNSCALE = 1.f / 64.f;
// GEMM smem: sS 32 x 260 f32 = 33280 B, then 3 stages of 24 KB (A 8K|B0 8K|B1 8K)
constexpr int SM_ST    = 33280;
constexpr int STAGE_B  = 24576;
constexpr int SM_TOTAL = SM_ST + 3 * STAGE_B;   // 107008
}

__device__ float g_V3[R * NB];
__device__ float g_u2[R * NB];
__device__ float g_u1[R * NB];
// A blocks: [mt(8)][kc(16)] x 2048 words ; B blocks: [nt(32)][kc(16)] x 2048 words
__device__ uint32_t g_A1[8 * 16 * 2048];
__device__ uint32_t g_A2[8 * 16 * 2048];
__device__ uint32_t g_B0[32 * 16 * 2048];
__device__ uint32_t g_B1[32 * 16 * 2048];

// ---------------------------------------------------------------------------
__device__ __forceinline__ uint32_t smem_u32(const void* p) {
    uint32_t a;
    asm("{ .reg .u64 t; cvta.to.shared.u64 t, %1; cvt.u32.u64 %0, t; }" : "=r"(a) : "l"(p));
    return a;
}
__device__ __forceinline__ void cp16(uint32_t saddr, const void* g) {
    asm volatile("cp.async.cg.shared.global [%0], [%1], 16;" :: "r"(saddr), "l"(g) : "memory");
}
#define CP_COMMIT() asm volatile("cp.async.commit_group;" ::: "memory")

__device__ __forceinline__ void mma16816(float* d, const uint32_t* a, const uint32_t* b) {
    asm volatile(
        "mma.sync.aligned.m16n8k16.row.col.f32.f16.f16.f32 "
        "{%0,%1,%2,%3}, {%4,%5,%6,%7}, {%8,%9}, {%0,%1,%2,%3};"
        : "+f"(d[0]), "+f"(d[1]), "+f"(d[2]), "+f"(d[3])
        : "r"(a[0]), "r"(a[1]), "r"(a[2]), "r"(a[3]), "r"(b[0]), "r"(b[1]));
}
__device__ __forceinline__ void ldsm4(uint32_t* r, uint32_t saddr) {
    asm volatile("ldmatrix.sync.aligned.m8n8.x4.shared.b16 {%0,%1,%2,%3}, [%4];"
                 : "=r"(r[0]), "=r"(r[1]), "=r"(r[2]), "=r"(r[3]) : "r"(saddr));
}
__device__ __forceinline__ uint32_t h2pack(__half a, __half b) {
    return ((uint32_t)__half_as_ushort(b) << 16) | __half_as_ushort(a);
}
__device__ __forceinline__ uint32_t pack_af(float x0, float x1) {
    return h2pack(__float2half_rn(x0 * ASCALE), __float2half_rn(x1 * ASCALE));
}
__device__ __forceinline__ uint32_t pack_bf(float x0, float x1) {
    return h2pack(__float2half_rn(x0), __float2half_rn(x1));
}

// ---------------------------------------------------------------------------
// Pack both cores -> A blocks. grid (mt=8, kc=16, z=2), 256 thr.
// z=0: core1 -> g_A1 ; z=1: core2 -> g_A2.
// ---------------------------------------------------------------------------
__global__ __launch_bounds__(256)
void pack_core_kernel(const float* __restrict__ c1, const float* __restrict__ c2)
{
    const float* __restrict__ core = (blockIdx.z == 0) ? c1 : c2;
    uint32_t* __restrict__ out     = (blockIdx.z == 0) ? g_A1 : g_A2;
    __shared__ float sC[4 * 1056];    // [a_loc][kloc(32) stride 33][b(32)]
    const int t = threadIdx.x, mt = blockIdx.x, kc = blockIdx.y;
#pragma unroll
    for (int i = 0; i < 16; i++) {
        int idx = t + i * 256;                 // 0..4095
        int a_loc = idx >> 10, rem = idx & 1023;
        int kloc = rem >> 5, b = rem & 31;
        sC[a_loc * 1056 + kloc * 33 + b] =
            core[(mt * 4 + a_loc) * (D * R) + kc * 1024 + rem];
    }
    __syncthreads();
    uint32_t* dst = out + (mt * 16 + kc) * 2048;
#pragma unroll
    for (int i = 0; i < 8; i++) {
        int w = t + i * 256;                   // 0..2047
        int m_loc = w >> 4, wsw = w & 15;
        int kp = wsw ^ ((m_loc & 3) << 2);
        int a_loc = m_loc >> 5, b = m_loc & 31, k0 = kp * 2;
        float x0 = sC[a_loc * 1056 + k0 * 33 + b];
        float x1 = sC[a_loc * 1056 + (k0 + 1) * 33 + b];
        dst[w] = pack_af(x0, x1);
    }
}

// ---------------------------------------------------------------------------
// Pack both X -> B blocks. grid (nt=32, kc=16, z=2), 256 thr.
// z=0: X0 -> g_B0 ; z=1: X1 -> g_B1.
// ---------------------------------------------------------------------------
__global__ __launch_bounds__(256)
void pack_x_kernel(const float* __restrict__ x0p, const float* __restrict__ x1p)
{
    const float* __restrict__ X = (blockIdx.z == 0) ? x0p : x1p;
    uint32_t* __restrict__ out  = (blockIdx.z == 0) ? g_B0 : g_B1;
    __shared__ float sX[32 * 129];
    const int t = threadIdx.x, nt = blockIdx.x, kc = blockIdx.y;
#pragma unroll
    for (int i = 0; i < 16; i++) {
        int idx = t + i * 256;
        int k = idx >> 7, nl = idx & 127;
        sX[k * 129 + nl] = X[(kc * 32 + k) * NB + nt * 128 + nl];
    }
    __syncthreads();
    uint32_t* dst = out + (nt * 16 + kc) * 2048;
#pragma unroll
    for (int i = 0; i < 8; i++) {
        int w = t + i * 256;                   // 0..2047
        int n_loc = w >> 4, wsw = w & 15;
        int kp = wsw ^ ((n_loc & 3) << 2);
        int k0 = kp * 2;
        dst[w] = pack_bf(sX[k0 * 129 + n_loc], sX[(k0 + 1) * 129 + n_loc]);
    }
}

// ---------------------------------------------------------------------------
// v3[a,n] = sum_d core3[a,d] * X2[d,n]   (writes g_V3 directly)
// ---------------------------------------------------------------------------
__global__ __launch_bounds__(256)
void v3_kernel(const float* __restrict__ core3, const float* __restrict__ X2)
{
    __shared__ float Xs[32][128];
    const int t = threadIdx.x, n0 = blockIdx.x * 128;
    const int nl = t & 127, ab = (t >> 7) * 16;
    float acc[16];
#pragma unroll
    for (int i = 0; i < 16; i++) acc[i] = 0.f;
    for (int d0 = 0; d0 < D; d0 += 32) {
#pragma unroll
        for (int i = 0; i < 16; i++) {
            int idx = t + i * 256;
            Xs[idx >> 7][idx & 127] = X2[(d0 + (idx >> 7)) * NB + n0 + (idx & 127)];
        }
        __syncthreads();
#pragma unroll
        for (int dl = 0; dl < 32; dl++) {
            float x = Xs[dl][nl];
#pragma unroll
            for (int i = 0; i < 16; i++)
                acc[i] += core3[(ab + i) * D + d0 + dl] * x;
        }
        __syncthreads();
    }
#pragma unroll
    for (int i = 0; i < 16; i++)
        g_V3[(ab + i) * NB + n0 + nl] = acc[i];
}

// ---------------------------------------------------------------------------
// Tensor GEMM 128m x 256n (fp16, ldmatrix, 3-stage) + fused contraction epi.
// grid (nq=16, mt=8) = 128 CTAs, 256 thr, 1 CTA/SM.
// warps: wm = warp&3 (32 m rows = one 'a'), wn = warp>>2 (selects 128-col B block).
// pass 0: A=g_A2, B=g_B1, scale=g_V3, out=g_u2
// pass 1: A=g_A1, B=g_B0, scale=g_u2, out=g_u1
// out[a, n] = (1/64) * sum_b C[a*32+b, n] * scale[b, n],  a = mt*4 + wm.
// ---------------------------------------------------------------------------
__global__ __launch_bounds__(256, 1)
void tt_gemm_kernel(int pass)
{
    const uint32_t* __restrict__ Apk   = (pass == 0) ? g_A2 : g_A1;
    const uint32_t* __restrict__ Bpk   = (pass == 0) ? g_B1 : g_B0;
    const float*    __restrict__ scale = (pass == 0) ? g_V3 : g_u2;
    float*          __restrict__ out   = (pass == 0) ? g_u2 : g_u1;

    extern __shared__ char smem[];
    const int t = threadIdx.x, warp = t >> 5, lane = t & 31;
    const int wm = warp & 3, wn = warp >> 2;
    const int g = lane >> 2, c = lane & 3;
    const int nq = blockIdx.x, mt = blockIdx.y;
    const uint32_t sbase = smem_u32(smem);

    // ldmatrix per-lane row geometry (loop-invariant)
    const int mat  = lane >> 3;          // 0..3
    const int mrow = lane & 7;
    const int hA = mat >> 1;                                     // A k-half
    const int rA0 = (wm * 2 + 0) * 16 + (mat & 1) * 8 + mrow;    // i=0 row
    const int rA1 = rA0 + 16;                                    // i=1 row
    const int hB = mat & 1;                                      // B k-half
    const int rB = (mat >> 1) * 8 + mrow;                        // + jp*8

    // scale tile: 32 x 256, stride 260
    float* sS = (float*)smem;
#pragma unroll
    for (int i = 0; i < 32; i++) {
        int idx = t + i * 256;
        sS[(idx >> 8) * 260 + (idx & 255)] = scale[(idx >> 8) * NB + nq * 256 + (idx & 255)];
    }

    const uint32_t* Asrc  = Apk + mt * 32768;             // 16 kc * 2048
    const uint32_t* B0src = Bpk + (nq * 2 + 0) * 32768;
    const uint32_t* B1src = Bpk + (nq * 2 + 1) * 32768;

    float acc[2][16][4];
#pragma unroll
    for (int i = 0; i < 2; i++)
#pragma unroll
        for (int j = 0; j < 16; j++)
#pragma unroll
            for (int q = 0; q < 4; q++) acc[i][j][q] = 0.f;

    // stage issue: A 2048 w | B0 2048 w | B1 2048 w (24 KB)
    auto issue = [&](int kc) {
        uint32_t sd = sbase + SM_ST + (kc % 3) * STAGE_B;
        const uint4* a4  = (const uint4*)(Asrc  + kc * 2048);
        const uint4* b04 = (const uint4*)(B0src + kc * 2048);
        const uint4* b14 = (const uint4*)(B1src + kc * 2048);
        cp16(sd + t * 16, a4 + t);
        cp16(sd + (t + 256) * 16, a4 + t + 256);
        cp16(sd + 8192 + t * 16, b04 + t);
        cp16(sd + 8192 + (t + 256) * 16, b04 + t + 256);
        cp16(sd + 16384 + t * 16, b14 + t);
        cp16(sd + 16384 + (t + 256) * 16, b14 + t + 256);
        CP_COMMIT();
    };
    issue(0);
    issue(1);

    for (int kc = 0; kc < 16; kc++) {
        if (kc < 15)
            asm volatile("cp.async.wait_group 1;" ::: "memory");
        else
            asm volatile("cp.async.wait_group 0;" ::: "memory");
        __syncthreads();                       // stage kc visible to all
        if (kc + 2 < 16) issue(kc + 2);        // overwrites stage (kc-1)%3: safe

        const uint32_t sA = sbase + SM_ST + (kc % 3) * STAGE_B;
        const uint32_t sB = sA + 8192 + wn * 8192;

#pragma unroll
        for (int ks = 0; ks < 2; ks++) {
            uint32_t ah[2][4];
            {
                uint32_t kgA = (uint32_t)(ks * 2 + hA);
                uint32_t w0 = rA0 * 16 + ((kgA ^ (rA0 & 3)) << 2);
                uint32_t w1 = rA1 * 16 + ((kgA ^ (rA1 & 3)) << 2);
                ldsm4(ah[0], sA + w0 * 4);
                ldsm4(ah[1], sA + w1 * 4);
            }
#pragma unroll
            for (int jp = 0; jp < 16; jp += 2) {
                uint32_t bb[4];
                {
                    int rn = rB + jp * 8;
                    uint32_t kgB = (uint32_t)(ks * 2 + hB);
                    uint32_t w = rn * 16 + ((kgB ^ (rn & 3)) << 2);
                    ldsm4(bb, sB + w * 4);
                }
#pragma unroll
                for (int i = 0; i < 2; i++) {
                    mma16816(acc[i][jp],     ah[i], bb);
                    mma16816(acc[i][jp + 1], ah[i], bb + 2);
                }
            }
        }
    }

    // epilogue: contract over b = rows of the warp's 32-row strip, unscale
    const int a = mt * 4 + wm;
    float* dst = out + a * NB + nq * 256 + wn * 128;
#pragma unroll
    for (int j = 0; j < 16; j++) {
        int col0 = wn * 128 + j * 8 + c * 2;
        float p0 = 0.f, p1 = 0.f;
#pragma unroll
        for (int i = 0; i < 2; i++) {
            int b0 = i * 16 + g, b1 = b0 + 8;
            p0 += acc[i][j][0] * sS[b0 * 260 + col0] + acc[i][j][2] * sS[b1 * 260 + col0];
            p1 += acc[i][j][1] * sS[b0 * 260 + col0 + 1] + acc[i][j][3] * sS[b1 * 260 + col0 + 1];
        }
#pragma unroll
        for (int off = 4; off <= 16; off <<= 1) {
            p0 += __shfl_xor_sync(0xffffffffu, p0, off);
            p1 += __shfl_xor_sync(0xffffffffu, p1, off);
        }
        if (g == 0)
            *(float2*)&dst[j * 8 + c * 2] = make_float2(p0 * UNSCALE, p1 * UNSCALE);
    }
}

// ---------------------------------------------------------------------------
// Z[o,n] = sum_a core0[o*32+a] * u1[a,n]   (reads g_u1 directly)
// ---------------------------------------------------------------------------
__global__ __launch_bounds__(256)
void z_kernel(const float* __restrict__ core0, float* __restrict__ Z)
{
    __shared__ float cs[64 * 32];
    __shared__ float u1s[32][133];
    const int t = threadIdx.x, nt = blockIdx.x, og = blockIdx.y;
    const int n0 = nt * 128;
#pragma unroll
    for (int i = 0; i < 8; i++)
        cs[i * 256 + t] = core0[og * 64 * 32 + i * 256 + t];
#pragma unroll
    for (int i = 0; i < 16; i++) {
        int idx = t + i * 256;
        u1s[idx >> 7][idx & 127] = g_u1[(idx >> 7) * NB + n0 + (idx & 127)];
    }
    __syncthreads();
    const int j = t & 127, to = t >> 7;
    float u1r[32];
#pragma unroll
    for (int a = 0; a < 32; a++) u1r[a] = u1s[a][j];
#pragma unroll 4
    for (int oo = 0; oo < 32; oo++) {
        int ol = to * 32 + oo;
        float acc = 0.f;
#pragma unroll
        for (int a = 0; a < 32; a++)
            acc += cs[ol * 32 + a] * u1r[a];
        Z[(og * 64 + ol) * NB + n0 + j] = acc;
    }
}

// ---------------------------------------------------------------------------
extern "C" void kernel_launch(void* const* d_in, const int* in_sizes, int n_in,
                              void* d_out, int out_size)
{
    const float* X0    = (const float*)d_in[0];
    const float* X1    = (const float*)d_in[1];
    const float* X2    = (const float*)d_in[2];
    const float* core0 = (const float*)d_in[3];
    const float* core1 = (const float*)d_in[4];
    const float* core2 = (const float*)d_in[5];
    const float* core3 = (const float*)d_in[6];
    float* Z = (float*)d_out;

    static bool attr_done = false;
    if (!attr_done) {
        cudaFuncSetAttribute(tt_gemm_kernel,
                             cudaFuncAttributeMaxDynamicSharedMemorySize, SM_TOTAL);
        attr_done = true;
    }

    pack_core_kernel<<<dim3(8, 16, 2), 256>>>(core1, core2);
    pack_x_kernel<<<dim3(32, 16, 2), 256>>>(X0, X1);
    v3_kernel<<<32, 256>>>(core3, X2);
    tt_gemm_kernel<<<dim3(16, 8), 256, SM_TOTAL>>>(0);  // core2 x X1, scale v3 -> u2
    tt_gemm_kernel<<<dim3(16, 8), 256, SM_TOTAL>>>(1);  // core1 x X0, scale u2 -> u1
    z_kernel<<<dim3(32, 8), 256>>>(core0, Z);
}

// round 11
// speedup vs baseline: 3.5563x; 1.2652x over previous
#include <cuda_runtime.h>
#include <cuda_fp16.h>
#include <cstdint>

// ============================================================================
// TensorTrain forward via mma.sync (single fp16 term) + fused rank contraction.
//   v3 = core3 @ X2                                   [32,4096]
//   GEMM pass0: perm(core2)@X1 tiles, epi * v3 -> u2  [32,4096]
//   GEMM pass1: perm(core1)@X0 tiles, epi * u2 -> u1  [32,4096]
//   Z = core0 @ u1                                    [512,4096]
//
// A (cores) pre-scaled x64, fp16; B (X) fp16. D = A*B (f32 accum), epi x 1/64.
// GEMM CTA tile: 128m x 256n, grid (16 nq, 8 mt) = 128 CTAs, 3-stage cp.async.
//
// Packed GLOBAL layout per (tile, kc=32k) block of 2048 u32 words (dense):
//   word[row*16 + kp] = f16pair(M[row][2kp], M[row][2kp+1]),  kp in 0..15.
// SMEM stage layout pads each 64 B row to 80 B (stride 20 words):
//   bankgroup(row, kg) = (5*row + kg) mod 8  -> 8 rows of every ldmatrix
//   8x8 tile hit 8 distinct bank groups: conflict-free (5 coprime 8).
// __device__ globals are ONLY referenced from device code (selected by flag).
// ============================================================================

namespace {
constexpr int NB = 4096;
constexpr int D  = 512;
constexpr int R  = 32;
constexpr float ASCALE  = 64.f;
constexpr float UNSCALE = 1.f / 64.f;
// GEMM smem: sS 32 x 260 f32 = 33280 B, then 3 stages of 30720 B
// (A 2560 w | B0 2560 w | B1 2560 w, 80 B row stride)
constexpr int SM_ST    = 33280;
constexpr int TILE_B   = 10240;             // padded tile bytes (128 rows * 80)
constexpr int STAGE_B  = 3 * TILE_B;        // 30720
constexpr int SM_TOTAL = SM_ST + 3 * STAGE_B;   // 125440
}

__device__ float g_V3[R * NB];
__device__ float g_u2[R * NB];
__device__ float g_u1[R * NB];
// A blocks: [mt(8)][kc(16)] x 2048 words ; B blocks: [nt(32)][kc(16)] x 2048 words
__device__ uint32_t g_A1[8 * 16 * 2048];
__device__ uint32_t g_A2[8 * 16 * 2048];
__device__ uint32_t g_B0[32 * 16 * 2048];
__device__ uint32_t g_B1[32 * 16 * 2048];

// ---------------------------------------------------------------------------
__device__ __forceinline__ uint32_t smem_u32(const void* p) {
    uint32_t a;
    asm("{ .reg .u64 t; cvta.to.shared.u64 t, %1; cvt.u32.u64 %0, t; }" : "=r"(a) : "l"(p));
    return a;
}
__device__ __forceinline__ void cp16(uint32_t saddr, const void* g) {
    asm volatile("cp.async.cg.shared.global [%0], [%1], 16;" :: "r"(saddr), "l"(g) : "memory");
}
#define CP_COMMIT() asm volatile("cp.async.commit_group;" ::: "memory")

__device__ __forceinline__ void mma16816(float* d, const uint32_t* a, const uint32_t* b) {
    asm volatile(
        "mma.sync.aligned.m16n8k16.row.col.f32.f16.f16.f32 "
        "{%0,%1,%2,%3}, {%4,%5,%6,%7}, {%8,%9}, {%0,%1,%2,%3};"
        : "+f"(d[0]), "+f"(d[1]), "+f"(d[2]), "+f"(d[3])
        : "r"(a[0]), "r"(a[1]), "r"(a[2]), "r"(a[3]), "r"(b[0]), "r"(b[1]));
}
__device__ __forceinline__ void ldsm4(uint32_t* r, uint32_t saddr) {
    asm volatile("ldmatrix.sync.aligned.m8n8.x4.shared.b16 {%0,%1,%2,%3}, [%4];"
                 : "=r"(r[0]), "=r"(r[1]), "=r"(r[2]), "=r"(r[3]) : "r"(saddr));
}
__device__ __forceinline__ uint32_t h2pack(__half a, __half b) {
    return ((uint32_t)__half_as_ushort(b) << 16) | __half_as_ushort(a);
}
__device__ __forceinline__ uint32_t pack_af(float x0, float x1) {
    return h2pack(__float2half_rn(x0 * ASCALE), __float2half_rn(x1 * ASCALE));
}
__device__ __forceinline__ uint32_t pack_bf(float x0, float x1) {
    return h2pack(__float2half_rn(x0), __float2half_rn(x1));
}

// ---------------------------------------------------------------------------
// Pack both cores -> A blocks (dense). grid (mt=8, kc=16, z=2), 256 thr.
// z=0: core1 -> g_A1 ; z=1: core2 -> g_A2.
// ---------------------------------------------------------------------------
__global__ __launch_bounds__(256)
void pack_core_kernel(const float* __restrict__ c1, const float* __restrict__ c2)
{
    const float* __restrict__ core = (blockIdx.z == 0) ? c1 : c2;
    uint32_t* __restrict__ out     = (blockIdx.z == 0) ? g_A1 : g_A2;
    __shared__ float sC[4 * 1056];    // [a_loc][kloc(32) stride 33][b(32)]
    const int t = threadIdx.x, mt = blockIdx.x, kc = blockIdx.y;
#pragma unroll
    for (int i = 0; i < 16; i++) {
        int idx = t + i * 256;                 // 0..4095
        int a_loc = idx >> 10, rem = idx & 1023;
        int kloc = rem >> 5, b = rem & 31;
        sC[a_loc * 1056 + kloc * 33 + b] =
            core[(mt * 4 + a_loc) * (D * R) + kc * 1024 + rem];
    }
    __syncthreads();
    uint32_t* dst = out + (mt * 16 + kc) * 2048;
#pragma unroll
    for (int i = 0; i < 8; i++) {
        int w = t + i * 256;                   // 0..2047
        int m_loc = w >> 4, kp = w & 15;
        int a_loc = m_loc >> 5, b = m_loc & 31, k0 = kp * 2;
        float x0 = sC[a_loc * 1056 + k0 * 33 + b];
        float x1 = sC[a_loc * 1056 + (k0 + 1) * 33 + b];
        dst[w] = pack_af(x0, x1);
    }
}

// ---------------------------------------------------------------------------
// Pack both X -> B blocks (dense). grid (nt=32, kc=16, z=2), 256 thr.
// z=0: X0 -> g_B0 ; z=1: X1 -> g_B1.
// ---------------------------------------------------------------------------
__global__ __launch_bounds__(256)
void pack_x_kernel(const float* __restrict__ x0p, const float* __restrict__ x1p)
{
    const float* __restrict__ X = (blockIdx.z == 0) ? x0p : x1p;
    uint32_t* __restrict__ out  = (blockIdx.z == 0) ? g_B0 : g_B1;
    __shared__ float sX[32 * 129];
    const int t = threadIdx.x, nt = blockIdx.x, kc = blockIdx.y;
#pragma unroll
    for (int i = 0; i < 16; i++) {
        int idx = t + i * 256;
        int k = idx >> 7, nl = idx & 127;
        sX[k * 129 + nl] = X[(kc * 32 + k) * NB + nt * 128 + nl];
    }
    __syncthreads();
    uint32_t* dst = out + (nt * 16 + kc) * 2048;
#pragma unroll
    for (int i = 0; i < 8; i++) {
        int w = t + i * 256;                   // 0..2047
        int n_loc = w >> 4, kp = w & 15;
        int k0 = kp * 2;
        dst[w] = pack_bf(sX[k0 * 129 + n_loc], sX[(k0 + 1) * 129 + n_loc]);
    }
}

// ---------------------------------------------------------------------------
// v3[a,n] = sum_d core3[a,d] * X2[d,n].  grid 256 CTAs (16 cols each), 256 thr.
// ---------------------------------------------------------------------------
__global__ __launch_bounds__(256)
void v3_kernel(const float* __restrict__ core3, const float* __restrict__ X2)
{
    __shared__ float Xs[64][17];
    const int t = threadIdx.x, n0 = blockIdx.x * 16;
    const int a = t >> 3, ncp = (t & 7) * 2;
    float acc0 = 0.f, acc1 = 0.f;
    for (int d0 = 0; d0 < D; d0 += 64) {
#pragma unroll
        for (int i = 0; i < 4; i++) {
            int idx = t + i * 256;
            Xs[idx >> 4][idx & 15] = X2[(d0 + (idx >> 4)) * NB + n0 + (idx & 15)];
        }
        __syncthreads();
#pragma unroll
        for (int dl = 0; dl < 64; dl++) {
            float cv = core3[a * D + d0 + dl];
            acc0 += cv * Xs[dl][ncp];
            acc1 += cv * Xs[dl][ncp + 1];
        }
        __syncthreads();
    }
    g_V3[a * NB + n0 + ncp]     = acc0;
    g_V3[a * NB + n0 + ncp + 1] = acc1;
}

// ---------------------------------------------------------------------------
// Tensor GEMM 128m x 256n (fp16, ldmatrix, 3-stage, 80B-padded smem rows).
// grid (nq=16, mt=8) = 128 CTAs, 256 thr.
// warps: wm = warp&3 (32 m rows = one 'a'), wn = warp>>2 (128-col B block).
// pass 0: A=g_A2, B=g_B1, scale=g_V3, out=g_u2
// pass 1: A=g_A1, B=g_B0, scale=g_u2, out=g_u1
// out[a, n] = (1/64) * sum_b C[a*32+b, n] * scale[b, n],  a = mt*4 + wm.
// ---------------------------------------------------------------------------
__global__ __launch_bounds__(256, 1)
void tt_gemm_kernel(int pass)
{
    const uint32_t* __restrict__ Apk   = (pass == 0) ? g_A2 : g_A1;
    const uint32_t* __restrict__ Bpk   = (pass == 0) ? g_B1 : g_B0;
    const float*    __restrict__ scale = (pass == 0) ? g_V3 : g_u2;
    float*          __restrict__ out   = (pass == 0) ? g_u2 : g_u1;

    extern __shared__ char smem[];
    const int t = threadIdx.x, warp = t >> 5, lane = t & 31;
    const int wm = warp & 3, wn = warp >> 2;
    const int g = lane >> 2, c = lane & 3;
    const int nq = blockIdx.x, mt = blockIdx.y;
    const uint32_t sbase = smem_u32(smem);

    // ldmatrix per-lane row geometry (loop-invariant)
    const int mat  = lane >> 3;          // 0..3
    const int mrow = lane & 7;
    const int hA = mat >> 1;                                     // A k-half
    const int rA0 = (wm * 2 + 0) * 16 + (mat & 1) * 8 + mrow;    // i=0 row
    const int rA1 = rA0 + 16;                                    // i=1 row
    const int hB = mat & 1;                                      // B k-half
    const int rB = (mat >> 1) * 8 + mrow;                        // + jp*8

    // scale tile: 32 x 256, stride 260
    float* sS = (float*)smem;
#pragma unroll
    for (int i = 0; i < 32; i++) {
        int idx = t + i * 256;
        sS[(idx >> 8) * 260 + (idx & 255)] = scale[(idx >> 8) * NB + nq * 256 + (idx & 255)];
    }

    const uint32_t* Asrc  = Apk + mt * 32768;             // 16 kc * 2048
    const uint32_t* B0src = Bpk + (nq * 2 + 0) * 32768;
    const uint32_t* B1src = Bpk + (nq * 2 + 1) * 32768;

    float acc[2][16][4];
#pragma unroll
    for (int i = 0; i < 2; i++)
#pragma unroll
        for (int j = 0; j < 16; j++)
#pragma unroll
            for (int q = 0; q < 4; q++) acc[i][j][q] = 0.f;

    // padded smem offsets for this thread's two 16B chunks (i = t, t+256)
    const uint32_t o1 = (uint32_t)t * 16 + (uint32_t)(t & ~3) * 4;  // i*16 + (i>>2)*16
    const uint32_t o2 = o1 + 5120;

    auto issue = [&](int kc) {
        uint32_t sd = sbase + SM_ST + (kc % 3) * STAGE_B;
        const uint4* a4  = (const uint4*)(Asrc  + kc * 2048);
        const uint4* b04 = (const uint4*)(B0src + kc * 2048);
        const uint4* b14 = (const uint4*)(B1src + kc * 2048);
        cp16(sd + o1, a4 + t);
        cp16(sd + o2, a4 + t + 256);
        cp16(sd + TILE_B + o1, b04 + t);
        cp16(sd + TILE_B + o2, b04 + t + 256);
        cp16(sd + 2 * TILE_B + o1, b14 + t);
        cp16(sd + 2 * TILE_B + o2, b14 + t + 256);
        CP_COMMIT();
    };
    issue(0);
    issue(1);

    for (int kc = 0; kc < 16; kc++) {
        if (kc < 15)
            asm volatile("cp.async.wait_group 1;" ::: "memory");
        else
            asm volatile("cp.async.wait_group 0;" ::: "memory");
        __syncthreads();                       // stage kc visible to all
        if (kc + 2 < 16) issue(kc + 2);        // overwrites stage (kc-1)%3: safe

        const uint32_t sA = sbase + SM_ST + (kc % 3) * STAGE_B;
        const uint32_t sB = sA + TILE_B + wn * TILE_B;

#pragma unroll
        for (int ks = 0; ks < 2; ks++) {
            uint32_t ah[2][4];
            {
                uint32_t kgA = (uint32_t)(ks * 2 + hA);
                ldsm4(ah[0], sA + (uint32_t)rA0 * 80 + kgA * 16);
                ldsm4(ah[1], sA + (uint32_t)rA1 * 80 + kgA * 16);
            }
#pragma unroll
            for (int jp = 0; jp < 16; jp += 2) {
                uint32_t bb[4];
                {
                    int rn = rB + jp * 8;
                    uint32_t kgB = (uint32_t)(ks * 2 + hB);
                    ldsm4(bb, sB + (uint32_t)rn * 80 + kgB * 16);
                }
#pragma unroll
                for (int i = 0; i < 2; i++) {
                    mma16816(acc[i][jp],     ah[i], bb);
                    mma16816(acc[i][jp + 1], ah[i], bb + 2);
                }
            }
        }
    }

    // epilogue: contract over b = rows of the warp's 32-row strip, unscale
    const int a = mt * 4 + wm;
    float* dst = out + a * NB + nq * 256 + wn * 128;
#pragma unroll
    for (int j = 0; j < 16; j++) {
        int col0 = wn * 128 + j * 8 + c * 2;
        float p0 = 0.f, p1 = 0.f;
#pragma unroll
        for (int i = 0; i < 2; i++) {
            int b0 = i * 16 + g, b1 = b0 + 8;
            p0 += acc[i][j][0] * sS[b0 * 260 + col0] + acc[i][j][2] * sS[b1 * 260 + col0];
            p1 += acc[i][j][1] * sS[b0 * 260 + col0 + 1] + acc[i][j][3] * sS[b1 * 260 + col0 + 1];
        }
#pragma unroll
        for (int off = 4; off <= 16; off <<= 1) {
            p0 += __shfl_xor_sync(0xffffffffu, p0, off);
            p1 += __shfl_xor_sync(0xffffffffu, p1, off);
        }
        if (g == 0)
            *(float2*)&dst[j * 8 + c * 2] = make_float2(p0 * UNSCALE, p1 * UNSCALE);
    }
}

// ---------------------------------------------------------------------------
// Z[o,n] = sum_a core0[o*32+a] * u1[a,n]   (reads g_u1 directly)
// ---------------------------------------------------------------------------
__global__ __launch_bounds__(256)
void z_kernel(const float* __restrict__ core0, float* __restrict__ Z)
{
    __shared__ float cs[64 * 32];
    __shared__ float u1s[32][133];
    const int t = threadIdx.x, nt = blockIdx.x, og = blockIdx.y;
    const int n0 = nt * 128;
#pragma unroll
    for (int i = 0; i < 8; i++)
        cs[i * 256 + t] = core0[og * 64 * 32 + i * 256 + t];
#pragma unroll
    for (int i = 0; i < 16; i++) {
        int idx = t + i * 256;
        u1s[idx >> 7][idx & 127] = g_u1[(idx >> 7) * NB + n0 + (idx & 127)];
    }
    __syncthreads();
    const int j = t & 127, to = t >> 7;
    float u1r[32];
#pragma unroll
    for (int a = 0; a < 32; a++) u1r[a] = u1s[a][j];
#pragma unroll 4
    for (int oo = 0; oo < 32; oo++) {
        int ol = to * 32 + oo;
        float acc = 0.f;
#pragma unroll
        for (int a = 0; a < 32; a++)
            acc += cs[ol * 32 + a] * u1r[a];
        Z[(og * 64 + ol) * NB + n0 + j] = acc;
    }
}

// ---------------------------------------------------------------------------
extern "C" void kernel_launch(void* const* d_in, const int* in_sizes, int n_in,
                              void* d_out, int out_size)
{
    const float* X0    = (const float*)d_in[0];
    const float* X1    = (const float*)d_in[1];
    const float* X2    = (const float*)d_in[2];
    const float* core0 = (const float*)d_in[3];
    const float* core1 = (const float*)d_in[4];
    const float* core2 = (const float*)d_in[5];
    const float* core3 = (const float*)d_in[6];
    float* Z = (float*)d_out;

    static bool attr_done = false;
    if (!attr_done) {
        cudaFuncSetAttribute(tt_gemm_kernel,
                             cudaFuncAttributeMaxDynamicSharedMemorySize, SM_TOTAL);
        attr_done = true;
    }

    pack_core_kernel<<<dim3(8, 16, 2), 256>>>(core1, core2);
    pack_x_kernel<<<dim3(32, 16, 2), 256>>>(X0, X1);
    v3_kernel<<<256, 256>>>(core3, X2);
    tt_gemm_kernel<<<dim3(16, 8), 256, SM_TOTAL>>>(0);  // core2 x X1, scale v3 -> u2
    tt_gemm_kernel<<<dim3(16, 8), 256, SM_TOTAL>>>(1);  // core1 x X0, scale u2 -> u1
    z_kernel<<<dim3(32, 8), 256>>>(core0, Z);
}

// round 12
// speedup vs baseline: 4.0294x; 1.1330x over previous
#include <cuda_runtime.h>
#include <cuda_fp16.h>
#include <cstdint>

// ============================================================================
// TensorTrain forward via mma.sync (single fp16 term) + fused rank contraction.
//   v3 = core3 @ X2                                   [32,4096]
//   GEMM pass0: perm(core2)@X1 tiles, epi * v3 -> u2  [32,4096]
//   GEMM pass1: perm(core1)@X0 tiles, epi * u2 -> u1  [32,4096]
//   Z = core0 @ u1                                    [512,4096]
//
// A (cores) pre-scaled x64, fp16; B (X) fp16. D = A*B (f32 accum), epi x 1/64.
// GEMM CTA tile: 128m x 256n, 512 threads (16 warps = 4/SMSP for latency
// hiding), grid (16 nq, 8 mt) = 128 CTAs, 3-stage cp.async.
//
// Packed GLOBAL layout per (tile, kc=32k) block of 2048 u32 words (dense):
//   word[row*16 + kp] = f16pair(M[row][2kp], M[row][2kp+1]),  kp in 0..15.
// SMEM stage pads each 64 B row to 80 B: bankgroup(row,kg) = (5*row+kg) mod 8
//   -> 8 rows of every ldmatrix 8x8 tile hit 8 distinct groups (5 coprime 8).
// __device__ globals are ONLY referenced from device code (selected by flag).
// ============================================================================

namespace {
constexpr int NB = 4096;
constexpr int D  = 512;
constexpr int R  = 32;
constexpr float ASCALE  = 64.f;
constexpr float UNSCALE = 1.f / 64.f;
// GEMM smem: sS 32 x 260 f32 = 33280 B, then 3 stages of 30720 B
constexpr int SM_ST    = 33280;
constexpr int TILE_B   = 10240;             // padded tile bytes (128 rows * 80)
constexpr int STAGE_B  = 3 * TILE_B;        // 30720
constexpr int SM_TOTAL = SM_ST + 3 * STAGE_B;   // 125440
}

__device__ float g_V3[R * NB];
__device__ float g_u2[R * NB];
__device__ float g_u1[R * NB];
// A blocks: [mt(8)][kc(16)] x 2048 words ; B blocks: [nt(32)][kc(16)] x 2048 words
__device__ uint32_t g_A1[8 * 16 * 2048];
__device__ uint32_t g_A2[8 * 16 * 2048];
__device__ uint32_t g_B0[32 * 16 * 2048];
__device__ uint32_t g_B1[32 * 16 * 2048];

// ---------------------------------------------------------------------------
__device__ __forceinline__ uint32_t smem_u32(const void* p) {
    uint32_t a;
    asm("{ .reg .u64 t; cvta.to.shared.u64 t, %1; cvt.u32.u64 %0, t; }" : "=r"(a) : "l"(p));
    return a;
}
__device__ __forceinline__ void cp16(uint32_t saddr, const void* g) {
    asm volatile("cp.async.cg.shared.global [%0], [%1], 16;" :: "r"(saddr), "l"(g) : "memory");
}
#define CP_COMMIT() asm volatile("cp.async.commit_group;" ::: "memory")

__device__ __forceinline__ void mma16816(float* d, const uint32_t* a, const uint32_t* b) {
    asm volatile(
        "mma.sync.aligned.m16n8k16.row.col.f32.f16.f16.f32 "
        "{%0,%1,%2,%3}, {%4,%5,%6,%7}, {%8,%9}, {%0,%1,%2,%3};"
        : "+f"(d[0]), "+f"(d[1]), "+f"(d[2]), "+f"(d[3])
        : "r"(a[0]), "r"(a[1]), "r"(a[2]), "r"(a[3]), "r"(b[0]), "r"(b[1]));
}
__device__ __forceinline__ void ldsm4(uint32_t* r, uint32_t saddr) {
    asm volatile("ldmatrix.sync.aligned.m8n8.x4.shared.b16 {%0,%1,%2,%3}, [%4];"
                 : "=r"(r[0]), "=r"(r[1]), "=r"(r[2]), "=r"(r[3]) : "r"(saddr));
}
__device__ __forceinline__ uint32_t h2pack(__half a, __half b) {
    return ((uint32_t)__half_as_ushort(b) << 16) | __half_as_ushort(a);
}
__device__ __forceinline__ uint32_t pack_af(float x0, float x1) {
    return h2pack(__float2half_rn(x0 * ASCALE), __float2half_rn(x1 * ASCALE));
}
__device__ __forceinline__ uint32_t pack_bf(float x0, float x1) {
    return h2pack(__float2half_rn(x0), __float2half_rn(x1));
}

// ---------------------------------------------------------------------------
// Pack both cores -> A blocks (dense). grid (mt=8, kc=16, z=2), 256 thr.
// ---------------------------------------------------------------------------
__global__ __launch_bounds__(256)
void pack_core_kernel(const float* __restrict__ c1, const float* __restrict__ c2)
{
    const float* __restrict__ core = (blockIdx.z == 0) ? c1 : c2;
    uint32_t* __restrict__ out     = (blockIdx.z == 0) ? g_A1 : g_A2;
    __shared__ float sC[4 * 1056];    // [a_loc][kloc(32) stride 33][b(32)]
    const int t = threadIdx.x, mt = blockIdx.x, kc = blockIdx.y;
#pragma unroll
    for (int i = 0; i < 16; i++) {
        int idx = t + i * 256;                 // 0..4095
        int a_loc = idx >> 10, rem = idx & 1023;
        int kloc = rem >> 5, b = rem & 31;
        sC[a_loc * 1056 + kloc * 33 + b] =
            core[(mt * 4 + a_loc) * (D * R) + kc * 1024 + rem];
    }
    __syncthreads();
    uint32_t* dst = out + (mt * 16 + kc) * 2048;
#pragma unroll
    for (int i = 0; i < 8; i++) {
        int w = t + i * 256;                   // 0..2047
        int m_loc = w >> 4, kp = w & 15;
        int a_loc = m_loc >> 5, b = m_loc & 31, k0 = kp * 2;
        float x0 = sC[a_loc * 1056 + k0 * 33 + b];
        float x1 = sC[a_loc * 1056 + (k0 + 1) * 33 + b];
        dst[w] = pack_af(x0, x1);
    }
}

// ---------------------------------------------------------------------------
// Pack both X -> B blocks (dense). grid (nt=32, kc=16, z=2), 256 thr.
// ---------------------------------------------------------------------------
__global__ __launch_bounds__(256)
void pack_x_kernel(const float* __restrict__ x0p, const float* __restrict__ x1p)
{
    const float* __restrict__ X = (blockIdx.z == 0) ? x0p : x1p;
    uint32_t* __restrict__ out  = (blockIdx.z == 0) ? g_B0 : g_B1;
    __shared__ float sX[32 * 129];
    const int t = threadIdx.x, nt = blockIdx.x, kc = blockIdx.y;
#pragma unroll
    for (int i = 0; i < 16; i++) {
        int idx = t + i * 256;
        int k = idx >> 7, nl = idx & 127;
        sX[k * 129 + nl] = X[(kc * 32 + k) * NB + nt * 128 + nl];
    }
    __syncthreads();
    uint32_t* dst = out + (nt * 16 + kc) * 2048;
#pragma unroll
    for (int i = 0; i < 8; i++) {
        int w = t + i * 256;                   // 0..2047
        int n_loc = w >> 4, kp = w & 15;
        int k0 = kp * 2;
        dst[w] = pack_bf(sX[k0 * 129 + n_loc], sX[(k0 + 1) * 129 + n_loc]);
    }
}

// ---------------------------------------------------------------------------
// v3[a,n] = sum_d core3[a,d] * X2[d,n].  grid 256 CTAs (16 cols each), 256 thr.
// ---------------------------------------------------------------------------
__global__ __launch_bounds__(256)
void v3_kernel(const float* __restrict__ core3, const float* __restrict__ X2)
{
    __shared__ float Xs[64][17];
    const int t = threadIdx.x, n0 = blockIdx.x * 16;
    const int a = t >> 3, ncp = (t & 7) * 2;
    float acc0 = 0.f, acc1 = 0.f;
    for (int d0 = 0; d0 < D; d0 += 64) {
#pragma unroll
        for (int i = 0; i < 4; i++) {
            int idx = t + i * 256;
            Xs[idx >> 4][idx & 15] = X2[(d0 + (idx >> 4)) * NB + n0 + (idx & 15)];
        }
        __syncthreads();
#pragma unroll
        for (int dl = 0; dl < 64; dl++) {
            float cv = core3[a * D + d0 + dl];
            acc0 += cv * Xs[dl][ncp];
            acc1 += cv * Xs[dl][ncp + 1];
        }
        __syncthreads();
    }
    g_V3[a * NB + n0 + ncp]     = acc0;
    g_V3[a * NB + n0 + ncp + 1] = acc1;
}

// ---------------------------------------------------------------------------
// Tensor GEMM 128m x 256n, 512 threads / 16 warps (4 per SMSP).
// warps: wm = warp&3 (32 m rows = one 'a'), wn = warp>>2 (64-col n slice).
// grid (nq=16, mt=8) = 128 CTAs. 3-stage cp.async, 80B-padded smem rows.
// pass 0: A=g_A2, B=g_B1, scale=g_V3, out=g_u2
// pass 1: A=g_A1, B=g_B0, scale=g_u2, out=g_u1
// out[a, n] = (1/64) * sum_b C[a*32+b, n] * scale[b, n],  a = mt*4 + wm.
// ---------------------------------------------------------------------------
__global__ __launch_bounds__(512, 1)
void tt_gemm_kernel(int pass)
{
    const uint32_t* __restrict__ Apk   = (pass == 0) ? g_A2 : g_A1;
    const uint32_t* __restrict__ Bpk   = (pass == 0) ? g_B1 : g_B0;
    const float*    __restrict__ scale = (pass == 0) ? g_V3 : g_u2;
    float*          __restrict__ out   = (pass == 0) ? g_u2 : g_u1;

    extern __shared__ char smem[];
    const int t = threadIdx.x, warp = t >> 5, lane = t & 31;
    const int wm = warp & 3, wn = warp >> 2;        // wn 0..3: 64-col slice
    const int g = lane >> 2, c = lane & 3;
    const int nq = blockIdx.x, mt = blockIdx.y;
    const uint32_t sbase = smem_u32(smem);

    // ldmatrix per-lane row geometry (loop-invariant)
    const int mat  = lane >> 3;          // 0..3
    const int mrow = lane & 7;
    const int hA = mat >> 1;                                     // A k-half
    const int rA0 = (wm * 2 + 0) * 16 + (mat & 1) * 8 + mrow;    // i=0 row
    const int rA1 = rA0 + 16;                                    // i=1 row
    const int hB = mat & 1;                                      // B k-half
    const int rB = (wn & 1) * 64 + (mat >> 1) * 8 + mrow;        // + jp*8

    // scale tile: 32 x 256, stride 260
    float* sS = (float*)smem;
#pragma unroll
    for (int i = 0; i < 16; i++) {
        int idx = t + i * 512;
        sS[(idx >> 8) * 260 + (idx & 255)] = scale[(idx >> 8) * NB + nq * 256 + (idx & 255)];
    }

    const uint32_t* Asrc  = Apk + mt * 32768;             // 16 kc * 2048
    const uint32_t* B0src = Bpk + (nq * 2 + 0) * 32768;
    const uint32_t* B1src = Bpk + (nq * 2 + 1) * 32768;

    float acc[2][8][4];
#pragma unroll
    for (int i = 0; i < 2; i++)
#pragma unroll
        for (int j = 0; j < 8; j++)
#pragma unroll
            for (int q = 0; q < 4; q++) acc[i][j][q] = 0.f;

    // padded smem offset for this thread's 16B chunk (chunk index = t, 512/tile)
    const uint32_t o1 = (uint32_t)t * 16 + (uint32_t)(t & ~3) * 4;  // i*16 + (i>>2)*16

    auto issue = [&](int kc) {
        uint32_t sd = sbase + SM_ST + (kc % 3) * STAGE_B;
        cp16(sd + o1,              (const uint4*)(Asrc  + kc * 2048) + t);
        cp16(sd + TILE_B + o1,     (const uint4*)(B0src + kc * 2048) + t);
        cp16(sd + 2 * TILE_B + o1, (const uint4*)(B1src + kc * 2048) + t);
        CP_COMMIT();
    };
    issue(0);
    issue(1);

    for (int kc = 0; kc < 16; kc++) {
        if (kc < 15)
            asm volatile("cp.async.wait_group 1;" ::: "memory");
        else
            asm volatile("cp.async.wait_group 0;" ::: "memory");
        __syncthreads();                       // stage kc visible to all
        if (kc + 2 < 16) issue(kc + 2);        // overwrites stage (kc-1)%3: safe

        const uint32_t sA = sbase + SM_ST + (kc % 3) * STAGE_B;
        const uint32_t sB = sA + TILE_B + (uint32_t)(wn >> 1) * TILE_B;

#pragma unroll
        for (int ks = 0; ks < 2; ks++) {
            uint32_t ah[2][4];
            {
                uint32_t kgA = (uint32_t)(ks * 2 + hA);
                ldsm4(ah[0], sA + (uint32_t)rA0 * 80 + kgA * 16);
                ldsm4(ah[1], sA + (uint32_t)rA1 * 80 + kgA * 16);
            }
#pragma unroll
            for (int jp = 0; jp < 8; jp += 2) {
                uint32_t bb[4];
                {
                    int rn = rB + jp * 8;
                    uint32_t kgB = (uint32_t)(ks * 2 + hB);
                    ldsm4(bb, sB + (uint32_t)rn * 80 + kgB * 16);
                }
#pragma unroll
                for (int i = 0; i < 2; i++) {
                    mma16816(acc[i][jp],     ah[i], bb);
                    mma16816(acc[i][jp + 1], ah[i], bb + 2);
                }
            }
        }
    }

    // epilogue: contract over b = rows of the warp's 32-row strip, unscale
    const int a = mt * 4 + wm;
    float* dst = out + a * NB + nq * 256 + wn * 64;
#pragma unroll
    for (int j = 0; j < 8; j++) {
        int col0 = wn * 64 + j * 8 + c * 2;
        float p0 = 0.f, p1 = 0.f;
#pragma unroll
        for (int i = 0; i < 2; i++) {
            int b0 = i * 16 + g, b1 = b0 + 8;
            p0 += acc[i][j][0] * sS[b0 * 260 + col0] + acc[i][j][2] * sS[b1 * 260 + col0];
            p1 += acc[i][j][1] * sS[b0 * 260 + col0 + 1] + acc[i][j][3] * sS[b1 * 260 + col0 + 1];
        }
#pragma unroll
        for (int off = 4; off <= 16; off <<= 1) {
            p0 += __shfl_xor_sync(0xffffffffu, p0, off);
            p1 += __shfl_xor_sync(0xffffffffu, p1, off);
        }
        if (g == 0)
            *(float2*)&dst[j * 8 + c * 2] = make_float2(p0 * UNSCALE, p1 * UNSCALE);
    }
}

// ---------------------------------------------------------------------------
// Z[o,n] = sum_a core0[o*32+a] * u1[a,n]   (reads g_u1 directly)
// ---------------------------------------------------------------------------
__global__ __launch_bounds__(256)
void z_kernel(const float* __restrict__ core0, float* __restrict__ Z)
{
    __shared__ float cs[64 * 32];
    __shared__ float u1s[32][133];
    const int t = threadIdx.x, nt = blockIdx.x, og = blockIdx.y;
    const int n0 = nt * 128;
#pragma unroll
    for (int i = 0; i < 8; i++)
        cs[i * 256 + t] = core0[og * 64 * 32 + i * 256 + t];
#pragma unroll
    for (int i = 0; i < 16; i++) {
        int idx = t + i * 256;
        u1s[idx >> 7][idx & 127] = g_u1[(idx >> 7) * NB + n0 + (idx & 127)];
    }
    __syncthreads();
    const int j = t & 127, to = t >> 7;
    float u1r[32];
#pragma unroll
    for (int a = 0; a < 32; a++) u1r[a] = u1s[a][j];
#pragma unroll 4
    for (int oo = 0; oo < 32; oo++) {
        int ol = to * 32 + oo;
        float acc = 0.f;
#pragma unroll
        for (int a = 0; a < 32; a++)
            acc += cs[ol * 32 + a] * u1r[a];
        Z[(og * 64 + ol) * NB + n0 + j] = acc;
    }
}

// ---------------------------------------------------------------------------
extern "C" void kernel_launch(void* const* d_in, const int* in_sizes, int n_in,
                              void* d_out, int out_size)
{
    const float* X0    = (const float*)d_in[0];
    const float* X1    = (const float*)d_in[1];
    const float* X2    = (const float*)d_in[2];
    const float* core0 = (const float*)d_in[3];
    const float* core1 = (const float*)d_in[4];
    const float* core2 = (const float*)d_in[5];
    const float* core3 = (const float*)d_in[6];
    float* Z = (float*)d_out;

    static bool attr_done = false;
    if (!attr_done) {
        cudaFuncSetAttribute(tt_gemm_kernel,
                             cudaFuncAttributeMaxDynamicSharedMemorySize, SM_TOTAL);
        attr_done = true;
    }

    pack_core_kernel<<<dim3(8, 16, 2), 256>>>(core1, core2);
    pack_x_kernel<<<dim3(32, 16, 2), 256>>>(X0, X1);
    v3_kernel<<<256, 256>>>(core3, X2);
    tt_gemm_kernel<<<dim3(16, 8), 512, SM_TOTAL>>>(0);  // core2 x X1, scale v3 -> u2
    tt_gemm_kernel<<<dim3(16, 8), 512, SM_TOTAL>>>(1);  // core1 x X0, scale u2 -> u1
    z_kernel<<<dim3(32, 8), 256>>>(core0, Z);
}